// round 11
// baseline (speedup 1.0000x reference)
#include <cuda_runtime.h>
#include <cuda_bf16.h>

#define HID    256
#define QLEN   64
#define NOPS   9
#define NCOLS  16
#define TSTEPS 4
#define NNUM   8
typedef unsigned long long ull;
typedef unsigned int u32;

// ops: SUM=0 COUNT=1 DIFF=2 GREATER=3 LESSER=4 AND=5 OR=6 ASSIGN=7 RESET=8

__device__ __forceinline__ void fma2(ull& acc, ull a, ull b) {
    asm("fma.rn.f32x2 %0, %1, %2, %0;" : "+l"(acc) : "l"(a), "l"(b));
}
__device__ __forceinline__ ull pack2(float lo, float hi) {
    ull u; asm("mov.b64 %0, {%1, %2};" : "=l"(u) : "f"(lo), "f"(hi)); return u;
}
__device__ __forceinline__ ull pack2u(u32 lo, u32 hi) {
    ull u; asm("mov.b64 %0, {%1, %2};" : "=l"(u) : "r"(lo), "r"(hi)); return u;
}
__device__ __forceinline__ void unpk(ull u, u32& lo, u32& hi) {
    asm("mov.b64 {%0, %1}, %2;" : "=r"(lo), "=r"(hi) : "l"(u));
}
__device__ __forceinline__ float2 unpack2(ull u) {
    float2 f; asm("mov.b64 {%0, %1}, %2;" : "=f"(f.x), "=f"(f.y) : "l"(u)); return f;
}
__device__ __forceinline__ float tanha(float x) {
    float y; asm("tanh.approx.f32 %0, %1;" : "=f"(y) : "f"(x)); return y;
}
__device__ __forceinline__ u32 bf2u(float a, float b) {
    __nv_bfloat162 p = __floats2bfloat162_rn(a, b);
    return *(u32*)&p;
}
__device__ __forceinline__ float dot4(float4 a, float4 b) {
    return a.x * b.x + a.y * b.y + a.z * b.z + a.w * b.w;
}

// ---------------- device-global scratch ----------------
#define NBLK 1184
__device__ float  g_px[QLEN * HID];
__device__ float  g_M1[HID * NOPS];
__device__ float  g_M2[HID * NCOLS];
__device__ float  g_aop[TSTEPS * NOPS];
__device__ float  g_acol[TSTEPS * NCOLS];
__device__ float  g_piv[2];
__device__ float  g_part[NBLK * 8];
__device__ u32    g_ctr;
__device__ float  g_q[HID];          // final RNN state
__device__ float  g_zz[NNUM * HID];  // pivot hidden states

// ============================================================
// k_prep: 89 blocks x 512 threads (split-K, 2 threads per output)
// ============================================================
__global__ void k_prep(const int* __restrict__ qids, const float* __restrict__ emb,
                       const float* __restrict__ Wx, const float* __restrict__ Whist,
                       const float* __restrict__ opemb, const float* __restrict__ colemb)
{
    __shared__ float xs[HID];
    int b = blockIdx.x, tid = threadIdx.x;
    int i = tid >> 1, half = tid & 1;

    const float* wrow;
    float* dst;
    if (b < QLEN) {
        if (tid < HID) xs[tid] = emb[(long)qids[b] * HID + tid];
        wrow = Wx + i * HID + half * 128;
        dst  = g_px + b * HID + i;
    } else if (b < QLEN + NOPS) {
        int o = b - QLEN;
        if (tid < HID) xs[tid] = opemb[o * HID + tid];
        wrow = Whist + i * 768 + half * 128;
        dst  = g_M1 + i * NOPS + o;
    } else {
        int c = b - QLEN - NOPS;
        if (tid < HID) xs[tid] = colemb[c * HID + tid];
        wrow = Whist + i * 768 + 256 + half * 128;
        dst  = g_M2 + i * NCOLS + c;
    }
    __syncthreads();
    const float4* w4 = (const float4*)wrow;
    const float4* x4 = (const float4*)(xs + half * 128);
    float s0 = 0.f, s1 = 0.f;
#pragma unroll
    for (int q = 0; q < 32; q += 2) {   // 32 float4s = full 128-col half (was 16: BUG)
        s0 += dot4(w4[q], x4[q]);
        s1 += dot4(w4[q + 1], x4[q + 1]);
    }
    float s = s0 + s1;
    s += __shfl_xor_sync(0xffffffffu, s, 1);
    if (half == 0) *dst = s;
}

// ============================================================
// k_rnn: single block, 512 threads — ONLY the 64-step RNN.
// thread: sub = tid&3 (64-col quarter), pr = tid>>2 (rows pr and pr+128).
// Row A (pr): 64 f32 weights in regs. Row B (pr+128): 64 bf16 weights in shared.
// h loads SHARED between both rows.
// ============================================================
#define RNT 512

// dynamic smem (floats)
#define R_WBS   0                       // 8 * 512 ulonglong2 = 16384 floats
#define R_PX    16384                   // 16384
#define R_HBUF  (R_PX + QLEN * HID)     // 512
#define R_FLOATS (R_HBUF + 2 * HID)
#define R_SMEM  (R_FLOATS * 4)

__global__ void __launch_bounds__(RNT, 1)
k_rnn(const int* __restrict__ lwi_g, const float* __restrict__ Wh)
{
    extern __shared__ float sm[];
    ulonglong2* wbs2 = (ulonglong2*)(sm + R_WBS);
    float* px   = sm + R_PX;
    float* hbuf = sm + R_HBUF;
    __shared__ int slwi[NNUM];
    __shared__ u32 zmask[QLEN];

    int tid = threadIdx.x;
    int sub = tid & 3, pr = tid >> 2;
    int c0 = sub * 64;

    if (tid < NNUM) slwi[tid] = lwi_g[tid];
    if (tid < 2 * HID) hbuf[tid] = 0.f;
    {
        const float4* src = (const float4*)g_px;
        float4* dst = (float4*)px;
        for (int q = tid; q < QLEN * HID / 4; q += RNT) dst[q] = src[q];
    }
    // weights
    ull wfA[32];
    {
        const float4* wA4 = (const float4*)(Wh + pr * HID + c0);
#pragma unroll
        for (int q = 0; q < 16; q++) {
            float4 a = wA4[q];
            wfA[2*q]   = pack2(a.x, a.y);
            wfA[2*q+1] = pack2(a.z, a.w);
        }
        const float4* wB4 = (const float4*)(Wh + (pr + 128) * HID + c0);
#pragma unroll
        for (int j = 0; j < 8; j++) {
            float4 a = wB4[2*j], b = wB4[2*j+1];
            ulonglong2 u;
            u.x = pack2u(bf2u(a.x, a.y), bf2u(a.z, a.w));
            u.y = pack2u(bf2u(b.x, b.y), bf2u(b.z, b.w));
            wbs2[j * RNT + tid] = u;
        }
    }
    __syncthreads();
    if (tid < QLEN) {
        u32 m = 0;
#pragma unroll
        for (int n = 0; n < NNUM; n++)
            if (slwi[n] == tid) m |= (1u << n);
        zmask[tid] = m;
    }
    __syncthreads();

    for (int step = 0; step < QLEN; step++) {
        const ulonglong2* hc4 = (const ulonglong2*)(hbuf + (step & 1) * HID + c0);
        ull a0 = 0ull, a1 = 0ull, b0 = 0ull, b1 = 0ull;
#pragma unroll
        for (int j = 0; j < 8; j++) {
            ulonglong2 h2a = hc4[2*j], h2b = hc4[2*j + 1];
            fma2(a0, wfA[4*j],     h2a.x);
            fma2(a1, wfA[4*j + 1], h2a.y);
            fma2(a0, wfA[4*j + 2], h2b.x);
            fma2(a1, wfA[4*j + 3], h2b.y);
            ulonglong2 wv = wbs2[j * RNT + tid];
            u32 u0, u1, u2, u3;
            unpk(wv.x, u0, u1);
            unpk(wv.y, u2, u3);
            fma2(b0, pack2u(u0 << 16, u0 & 0xffff0000u), h2a.x);
            fma2(b1, pack2u(u1 << 16, u1 & 0xffff0000u), h2a.y);
            fma2(b0, pack2u(u2 << 16, u2 & 0xffff0000u), h2b.x);
            fma2(b1, pack2u(u3 << 16, u3 & 0xffff0000u), h2b.y);
        }
        float2 fa0 = unpack2(a0), fa1 = unpack2(a1);
        float2 fb0 = unpack2(b0), fb1 = unpack2(b1);
        float sA = (fa0.x + fa0.y) + (fa1.x + fa1.y);
        float sB = (fb0.x + fb0.y) + (fb1.x + fb1.y);
        sA += __shfl_xor_sync(0xffffffffu, sA, 1);
        sA += __shfl_xor_sync(0xffffffffu, sA, 2);
        sB += __shfl_xor_sync(0xffffffffu, sB, 1);
        sB += __shfl_xor_sync(0xffffffffu, sB, 2);
        if (sub == 0) {
            float vA = tanha(sA + px[step * HID + pr]);
            float vB = tanha(sB + px[step * HID + 128 + pr]);
            float* dst = hbuf + ((step + 1) & 1) * HID;
            dst[pr] = vA;
            dst[128 + pr] = vB;
            u32 m = zmask[step];
            if (m) {
#pragma unroll
                for (int n = 0; n < NNUM; n++)
                    if ((m >> n) & 1u) {
                        g_zz[n * HID + pr] = vA;
                        g_zz[n * HID + 128 + pr] = vB;
                    }
            }
            if (step == QLEN - 1) { g_q[pr] = vA; g_q[128 + pr] = vB; }
        }
        __syncthreads();
    }
}

// ============================================================
// k_sel: single block, 512 threads — pivots + selector chain.
// ============================================================
__global__ void __launch_bounds__(512, 1)
k_sel(const int* __restrict__ nums_g, const float* __restrict__ Wop,
      const float* __restrict__ Wcol, const float* __restrict__ Whist,
      const float* __restrict__ opemb, const float* __restrict__ colemb,
      const float* __restrict__ Uv)
{
    __shared__ float zz[NNUM * HID];
    __shared__ float qpl[HID];
    __shared__ float hh[HID];
    __shared__ float uop[HID], ucol[HID], v3[HID], topo[HID], topc[HID];
    __shared__ float red[64];
    __shared__ float aop_s[16], acol_s[16];
    __shared__ float snum[NNUM];

    int tid  = threadIdx.x;
    int r    = tid >> 1, kh = tid & 1;
    int lane = tid & 31, wrp = tid >> 5;

    if (tid < NNUM) snum[tid] = (float)nums_g[tid];
    if (tid < HID)  { hh[tid] = 0.f; qpl[tid] = g_q[tid]; }
    for (int q = tid; q < NNUM * HID; q += 512) zz[q] = g_zz[q];
    __syncthreads();

    // ---- pivots: 16 warps cover (p,n) dot products ----
    {
        int p = wrp >> 3, n = wrp & 7;
        float s = 0.f;
#pragma unroll
        for (int j = 0; j < HID / 32; j++)
            s += zz[n * HID + j * 32 + lane] * Uv[p * HID + j * 32 + lane];
#pragma unroll
        for (int o = 16; o; o >>= 1) s += __shfl_xor_sync(0xffffffffu, s, o);
        if (lane == 0) red[p * 8 + n] = s;
    }
    __syncthreads();
    if (tid == 0) {
#pragma unroll
        for (int p = 0; p < 2; p++) {
            float m = -1e30f;
            for (int n = 0; n < 8; n++) m = fmaxf(m, red[p * 8 + n]);
            float den = 0.f, num = 0.f;
            for (int n = 0; n < 8; n++) {
                float e = expf(red[p * 8 + n] - m);
                den += e; num += e * snum[n];
            }
            g_piv[p] = num / den;
        }
    }

    // ---- timestep-invariant halves of W_op/W_col applied to q ----
    {
        const float4* q4 = (const float4*)(qpl + kh * 128);
        const float4* a4 = (const float4*)(Wop  + r * 512 + kh * 128);
        const float4* b4 = (const float4*)(Wcol + r * 512 + kh * 128);
        float s1 = 0.f, s2 = 0.f;
#pragma unroll
        for (int q = 0; q < 32; q++) {
            float4 h4 = q4[q];
            s1 += dot4(a4[q], h4);
            s2 += dot4(b4[q], h4);
        }
        s1 += __shfl_xor_sync(0xffffffffu, s1, 1);
        s2 += __shfl_xor_sync(0xffffffffu, s2, 1);
        if (kh == 0) { uop[r] = s1; ucol[r] = s2; }
    }
    __syncthreads();

    // ---- selector chain: 4 timesteps ----
    for (int t = 0; t < TSTEPS; t++) {
        {
            const float4* h4p = (const float4*)(hh + kh * 128);
            const float4* a4 = (const float4*)(Wop   + r * 512 + 256 + kh * 128);
            const float4* b4 = (const float4*)(Wcol  + r * 512 + 256 + kh * 128);
            const float4* c4 = (const float4*)(Whist + r * 768 + 512 + kh * 128);
            float s1 = 0.f, s2 = 0.f, s3 = 0.f;
#pragma unroll
            for (int q = 0; q < 32; q++) {
                float4 h4 = h4p[q];
                s1 += dot4(a4[q], h4);
                s2 += dot4(b4[q], h4);
                s3 += dot4(c4[q], h4);
            }
            s1 += __shfl_xor_sync(0xffffffffu, s1, 1);
            s2 += __shfl_xor_sync(0xffffffffu, s2, 1);
            s3 += __shfl_xor_sync(0xffffffffu, s3, 1);
            if (kh == 0) {
                topo[r] = tanha(uop[r] + s1);
                topc[r] = tanha(ucol[r] + s2);
                v3[r]   = s3;
            }
        }
        __syncthreads();
        if (wrp < NOPS) {
            float s = 0.f;
#pragma unroll
            for (int j = 0; j < HID / 32; j++)
                s += opemb[wrp * HID + j * 32 + lane] * topo[j * 32 + lane];
#pragma unroll
            for (int o = 16; o; o >>= 1) s += __shfl_xor_sync(0xffffffffu, s, o);
            if (lane == 0) red[wrp] = s;
        }
        {
            float s = 0.f;
#pragma unroll
            for (int j = 0; j < HID / 32; j++)
                s += colemb[wrp * HID + j * 32 + lane] * topc[j * 32 + lane];
#pragma unroll
            for (int o = 16; o; o >>= 1) s += __shfl_xor_sync(0xffffffffu, s, o);
            if (lane == 0) red[32 + wrp] = s;
        }
        __syncthreads();
        if (tid == 0) {
            float m = -1e30f;
            for (int o = 0; o < NOPS; o++) m = fmaxf(m, red[o]);
            float den = 0.f, e[NOPS];
            for (int o = 0; o < NOPS; o++) { e[o] = expf(red[o] - m); den += e[o]; }
            for (int o = 0; o < NOPS; o++) {
                float a = e[o] / den; aop_s[o] = a; g_aop[t * NOPS + o] = a;
            }
        }
        if (tid == 32) {
            float m = -1e30f;
            for (int c = 0; c < NCOLS; c++) m = fmaxf(m, red[32 + c]);
            float den = 0.f, e[NCOLS];
            for (int c = 0; c < NCOLS; c++) { e[c] = expf(red[32 + c] - m); den += e[c]; }
            for (int c = 0; c < NCOLS; c++) {
                float a = e[c] / den; acol_s[c] = a; g_acol[t * NCOLS + c] = a;
            }
        }
        __syncthreads();
        if (tid < HID) {
            float a = v3[tid];
#pragma unroll
            for (int o = 0; o < NOPS; o++)  a += g_M1[tid * NOPS + o] * aop_s[o];
#pragma unroll
            for (int c = 0; c < NCOLS; c++) a += g_M2[tid * NCOLS + c] * acol_s[c];
            hh[tid] = tanha(a);
        }
        __syncthreads();
    }
}

// ============================================================
// k_table: fused table pass + final reduction (last-block-done)
// ============================================================
#define K3T 256
__global__ void __launch_bounds__(K3T, 4)
k_table(const float* __restrict__ table, float* __restrict__ out, long rows)
{
    __shared__ ull   cf2[TSTEPS * NCOLS];
    __shared__ float cAnd[TSTEPS], cOr[TSTEPS], cRst[TSTEPS], cPass[TSTEPS];
    __shared__ float lkv[NCOLS];
    __shared__ float spv[2];
    __shared__ float wred[8 * 7];
    __shared__ int   sdone;
    __shared__ double sredd[7];

    int tid = threadIdx.x;
    if (tid < TSTEPS * NCOLS) {
        int t = tid >> 4, c = tid & 15;
        float ac = g_acol[t * NCOLS + c];
        cf2[tid] = pack2(g_aop[t * NOPS + 3] * ac, g_aop[t * NOPS + 4] * ac);
    } else if (tid < 64 + TSTEPS) {
        int t = tid - 64;
        cAnd[t]  = g_aop[t * NOPS + 5];
        cOr[t]   = g_aop[t * NOPS + 6];
        cRst[t]  = g_aop[t * NOPS + 8];
        cPass[t] = g_aop[t * NOPS + 0] + g_aop[t * NOPS + 1]
                 + g_aop[t * NOPS + 2] + g_aop[t * NOPS + 7];
    } else if (tid >= 96 && tid < 96 + NCOLS) {
        lkv[tid - 96] = g_aop[3 * NOPS + 7] * g_acol[3 * NCOLS + (tid - 96)];
    } else if (tid == 112) {
        spv[0] = g_piv[0]; spv[1] = g_piv[1];
    }
    __syncthreads();
    float lp = spv[0], gp = spv[1];
    int lane = tid & 31;
    float lkc = lkv[lane & 15];

    float accA = 0.f, aW0 = 0.f, aW1 = 0.f, aW2 = 0.f;
    float aC0 = 0.f, aC1 = 0.f, aC2 = 0.f;

    long stride = (long)gridDim.x * K3T;
    for (long base = (long)blockIdx.x * K3T; base < rows; base += stride) {
        long r = base + tid;
        float p1 = 0.f;
        if (r < rows) {
            const float4* tp = (const float4*)(table + r * NCOLS);
            float4 v0 = __ldcg(tp + 0), v1 = __ldcg(tp + 1);
            float4 v2 = __ldcg(tp + 2), v3r = __ldcg(tp + 3);
            float tv[16] = { v0.x, v0.y, v0.z, v0.w,  v1.x, v1.y, v1.z, v1.w,
                             v2.x, v2.y, v2.z, v2.w,  v3r.x, v3r.y, v3r.z, v3r.w };
            float rowsum = 0.f;
            ull acc0 = 0ull, acc1 = 0ull, acc2 = 0ull, acc3 = 0ull;
#pragma unroll
            for (int c = 0; c < 16; c++) {
                float v = tv[c];
                rowsum += v;
                float sg = fmaf(0.5f, tanha(0.5f * (v - gp)), 0.5f);
                float sl = fmaf(-0.5f, tanha(0.5f * (v - lp)), 0.5f);
                ull x = pack2(sg, sl);
                fma2(acc0, x, cf2[c]);
                fma2(acc1, x, cf2[16 + c]);
                fma2(acc2, x, cf2[32 + c]);
                fma2(acc3, x, cf2[48 + c]);
            }
            float2 d0 = unpack2(acc0), d1 = unpack2(acc1);
            float2 d2 = unpack2(acc2), d3 = unpack2(acc3);
            float d[4] = { d0.x + d0.y, d1.x + d1.y, d2.x + d2.y, d3.x + d3.y };
            accA += rowsum;
            float q1 = 1.f, q2 = 1.f;
#pragma unroll
            for (int t = 0; t < 4; t++) {
                float rs = d[t] + cAnd[t] * fminf(q1, q2)
                         + cOr[t] * fmaxf(q1, q2) + cRst[t] + cPass[t] * q1;
                if (t == 0) { aW0 += rs * rowsum; aC0 += rs; }
                else if (t == 1) { aW1 += rs * rowsum; aC1 += rs; }
                else if (t == 2) { aW2 += rs * rowsum; aC2 += rs; }
                q2 = q1; q1 = rs;
            }
            p1 = q1;
        }
        long rbase = base + (long)(tid & ~31);
        float* op = out + 1 + rbase * NCOLS;
#pragma unroll
        for (int m = 0; m < 16; m++) {
            int srcl = 2 * m + (lane >> 4);
            float v = __shfl_sync(0xffffffffu, p1, srcl);
            if (rbase + srcl < rows) op[m * 32 + lane] = v * lkc;
        }
    }

    float vals[7] = { accA, aW0, aW1, aW2, aC0, aC1, aC2 };
#pragma unroll
    for (int kk = 0; kk < 7; kk++) {
        float v = vals[kk];
#pragma unroll
        for (int o = 16; o; o >>= 1) v += __shfl_xor_sync(0xffffffffu, v, o);
        if ((tid & 31) == 0) wred[(tid >> 5) * 7 + kk] = v;
    }
    __syncthreads();
    if (tid < 7) {
        float s = 0.f;
        for (int wi = 0; wi < 8; wi++) s += wred[wi * 7 + tid];
        g_part[blockIdx.x * 8 + tid] = s;
    }
    __threadfence();
    __syncthreads();
    if (tid == 0) sdone = (atomicAdd(&g_ctr, 1u) == (u32)gridDim.x - 1u) ? 1 : 0;
    __syncthreads();
    if (!sdone) return;

    if (tid < 224) {
        int j = tid >> 5, ln = tid & 31;
        double s = 0.0;
        for (int b = ln; b < NBLK; b += 32) s += (double)g_part[b * 8 + j];
#pragma unroll
        for (int o = 16; o; o >>= 1) s += __shfl_xor_sync(0xffffffffu, s, o);
        if (ln == 0) sredd[j] = s;
    }
    __syncthreads();
    if (tid == 0) {
        double A   = sredd[0];
        double SW0 = sredd[1], SW1 = sredd[2], SW2 = sredd[3];
        double SC0 = sredd[4], SC1 = sredd[5], SC2 = sredd[6];
        const float* a0 = g_aop;
        const float* a1 = g_aop + NOPS;
        const float* a2 = g_aop + 2 * NOPS;
        const float* a3 = g_aop + 3 * NOPS;
        double s0 = (double)a0[0] * A   + (double)a0[1] * (double)rows;
        double s1 = (double)a1[0] * SW0 + (double)a1[1] * SC0 + (double)a1[2] * (0.0 - s0);
        double s2 = (double)a2[0] * SW1 + (double)a2[1] * SC1 + (double)a2[2] * (0.0 - s1);
        double s3 = (double)a3[0] * SW2 + (double)a3[1] * SC2 + (double)a3[2] * (s0 - s2);
        out[0] = (float)s3;
        g_ctr = 0u;
    }
}

// ============================================================
extern "C" void kernel_launch(void* const* d_in, const int* in_sizes, int n_in,
                              void* d_out, int out_size)
{
    const int*   qids   = (const int*)d_in[0];
    const int*   nums   = (const int*)d_in[1];
    const int*   lwi    = (const int*)d_in[2];
    const float* table  = (const float*)d_in[3];
    const float* emb    = (const float*)d_in[4];
    const float* Wx     = (const float*)d_in[5];
    const float* Wh     = (const float*)d_in[6];
    const float* Wop    = (const float*)d_in[7];
    const float* opemb  = (const float*)d_in[8];
    const float* Wcol   = (const float*)d_in[9];
    const float* colemb = (const float*)d_in[10];
    const float* Whist  = (const float*)d_in[11];
    const float* Uv     = (const float*)d_in[12];
    float* out = (float*)d_out;
    long rows = (long)in_sizes[3] / NCOLS;

    cudaFuncSetAttribute(k_rnn, cudaFuncAttributeMaxDynamicSharedMemorySize, R_SMEM);

    k_prep<<<QLEN + NOPS + NCOLS, 512>>>(qids, emb, Wx, Whist, opemb, colemb);
    k_rnn<<<1, RNT, R_SMEM>>>(lwi, Wh);
    k_sel<<<1, 512>>>(nums, Wop, Wcol, Whist, opemb, colemb, Uv);
    k_table<<<NBLK, K3T>>>(table, out, rows);
}

// round 12
// speedup vs baseline: 1.6951x; 1.6951x over previous
#include <cuda_runtime.h>
#include <cuda_bf16.h>

#define HID    256
#define QLEN   64
#define NOPS   9
#define NCOLS  16
#define TSTEPS 4
#define NNUM   8
typedef unsigned long long ull;
typedef unsigned int u32;

// ops: SUM=0 COUNT=1 DIFF=2 GREATER=3 LESSER=4 AND=5 OR=6 ASSIGN=7 RESET=8

__device__ __forceinline__ void fma2(ull& acc, ull a, ull b) {
    asm("fma.rn.f32x2 %0, %1, %2, %0;" : "+l"(acc) : "l"(a), "l"(b));
}
__device__ __forceinline__ ull pack2(float lo, float hi) {
    ull u; asm("mov.b64 %0, {%1, %2};" : "=l"(u) : "f"(lo), "f"(hi)); return u;
}
__device__ __forceinline__ ull pack2u(u32 lo, u32 hi) {
    ull u; asm("mov.b64 %0, {%1, %2};" : "=l"(u) : "r"(lo), "r"(hi)); return u;
}
__device__ __forceinline__ float2 unpack2(ull u) {
    float2 f; asm("mov.b64 {%0, %1}, %2;" : "=f"(f.x), "=f"(f.y) : "l"(u)); return f;
}
__device__ __forceinline__ float tanha(float x) {
    float y; asm("tanh.approx.f32 %0, %1;" : "=f"(y) : "f"(x)); return y;
}
__device__ __forceinline__ u32 bf2u(float a, float b) {
    __nv_bfloat162 p = __floats2bfloat162_rn(a, b);
    return *(u32*)&p;
}
__device__ __forceinline__ float dot4(float4 a, float4 b) {
    return a.x * b.x + a.y * b.y + a.z * b.z + a.w * b.w;
}
// D(16x8) += A(16x16,bf16,row) * B(16x8,bf16,col); f32 accum
__device__ __forceinline__ void mma_bf16(float* d, u32 a0, u32 a1, u32 a2, u32 a3,
                                         u32 b0, u32 b1) {
    asm volatile(
        "mma.sync.aligned.m16n8k16.row.col.f32.bf16.bf16.f32 "
        "{%0,%1,%2,%3}, {%4,%5,%6,%7}, {%8,%9}, {%0,%1,%2,%3};"
        : "+f"(d[0]), "+f"(d[1]), "+f"(d[2]), "+f"(d[3])
        : "r"(a0), "r"(a1), "r"(a2), "r"(a3), "r"(b0), "r"(b1));
}

// ---------------- device-global scratch ----------------
#define NBLK 1184
__device__ float  g_px[QLEN * HID];
__device__ float  g_M1[HID * NOPS];
__device__ float  g_M2[HID * NCOLS];
__device__ float  g_aop[TSTEPS * NOPS];
__device__ float  g_acol[TSTEPS * NCOLS];
__device__ float  g_piv[2];
__device__ float  g_part[NBLK * 8];
__device__ u32    g_ctr;
__device__ float  g_q[HID];          // final RNN state
__device__ float  g_zz[NNUM * HID];  // pivot hidden states

// ============================================================
// k_prep: 89 blocks x 512 threads (split-K, 2 threads per output)
// ============================================================
__global__ void k_prep(const int* __restrict__ qids, const float* __restrict__ emb,
                       const float* __restrict__ Wx, const float* __restrict__ Whist,
                       const float* __restrict__ opemb, const float* __restrict__ colemb)
{
    __shared__ float xs[HID];
    int b = blockIdx.x, tid = threadIdx.x;
    int i = tid >> 1, half = tid & 1;

    const float* wrow;
    float* dst;
    if (b < QLEN) {
        if (tid < HID) xs[tid] = emb[(long)qids[b] * HID + tid];
        wrow = Wx + i * HID + half * 128;
        dst  = g_px + b * HID + i;
    } else if (b < QLEN + NOPS) {
        int o = b - QLEN;
        if (tid < HID) xs[tid] = opemb[o * HID + tid];
        wrow = Whist + i * 768 + half * 128;
        dst  = g_M1 + i * NOPS + o;
    } else {
        int c = b - QLEN - NOPS;
        if (tid < HID) xs[tid] = colemb[c * HID + tid];
        wrow = Whist + i * 768 + 256 + half * 128;
        dst  = g_M2 + i * NCOLS + c;
    }
    __syncthreads();
    const float4* w4 = (const float4*)wrow;
    const float4* x4 = (const float4*)(xs + half * 128);
    float s0 = 0.f, s1 = 0.f;
#pragma unroll
    for (int q = 0; q < 32; q += 2) {
        s0 += dot4(w4[q], x4[q]);
        s1 += dot4(w4[q + 1], x4[q + 1]);
    }
    float s = s0 + s1;
    s += __shfl_xor_sync(0xffffffffu, s, 1);
    if (half == 0) *dst = s;
}

// ============================================================
// k_rnn: tensor-core RNN via mma.sync (bf16, f32 accum).
// 512 threads = 16 warps. Warp w owns rows 16w..16w+15; Wh A-frags in regs.
// h lives in shared as 64 u64 words in B-fragment layout, double-buffered.
// ============================================================
#define RNT 512

// dynamic smem layout (bytes): px[65536] | hb[2*512] | zmask[256] | slwi[32]
#define RB_PX    0
#define RB_HB    65536
#define RB_ZM    (RB_HB + 1024)
#define RB_SL    (RB_ZM + 256)
#define R_SMEM   (RB_SL + 32)

__global__ void __launch_bounds__(RNT, 1)
k_rnn(const int* __restrict__ lwi_g, const float* __restrict__ Wh)
{
    extern __shared__ char smraw[];
    float* px   = (float*)(smraw + RB_PX);
    ull*   hb   = (ull*)(smraw + RB_HB);     // [2][64]
    u32*  zmask = (u32*)(smraw + RB_ZM);
    int*  slwi  = (int*)(smraw + RB_SL);

    int tid = threadIdx.x;
    int w = tid >> 5, lane = tid & 31;
    int lg = lane >> 2, lt = lane & 3;       // group (0..7), thread-in-group (0..3)

    if (tid < NNUM) slwi[tid] = lwi_g[tid];
    if (tid < 64) hb[tid] = 0ull;            // buffer 0 = h_0 = 0
    {
        const float4* src = (const float4*)g_px;
        float4* dst = (float4*)px;
        for (int q = tid; q < QLEN * HID / 4; q += RNT) dst[q] = src[q];
    }
    __syncthreads();
    if (tid < QLEN) {
        u32 m = 0;
#pragma unroll
        for (int n = 0; n < NNUM; n++)
            if (slwi[n] == tid) m |= (1u << n);
        zmask[tid] = m;
    }

    // A-fragments: rows (16w+lg, 16w+lg+8), cols per k-tile
    u32 aF[64];
    {
        const float* Wr0 = Wh + (16 * w + lg) * HID;
        const float* Wr8 = Wh + (16 * w + lg + 8) * HID;
#pragma unroll
        for (int kt = 0; kt < 16; kt++) {
            int c = kt * 16 + 2 * lt;
            float2 x0 = *(const float2*)(Wr0 + c);
            float2 x1 = *(const float2*)(Wr8 + c);
            float2 x2 = *(const float2*)(Wr0 + c + 8);
            float2 x3 = *(const float2*)(Wr8 + c + 8);
            aF[4*kt + 0] = bf2u(x0.x, x0.y);
            aF[4*kt + 1] = bf2u(x1.x, x1.y);
            aF[4*kt + 2] = bf2u(x2.x, x2.y);
            aF[4*kt + 3] = bf2u(x3.x, x3.y);
        }
    }
    __syncthreads();

    int m1 = 16 * w + lg;                    // output rows this lane may own (lt==0)
    for (int step = 0; step < QLEN; step++) {
        const ull* hbc = hb + (step & 1) * 64;
        float d0[4] = {0.f, 0.f, 0.f, 0.f};
        float d1[4] = {0.f, 0.f, 0.f, 0.f};
        float d2[4] = {0.f, 0.f, 0.f, 0.f};
        float d3[4] = {0.f, 0.f, 0.f, 0.f};
#pragma unroll
        for (int kt = 0; kt < 16; kt++) {
            ull bb = hbc[kt * 4 + lt];
            u32 b0 = (u32)bb, b1 = (u32)(bb >> 32);
            float* dg = (kt & 3) == 0 ? d0 : (kt & 3) == 1 ? d1 : (kt & 3) == 2 ? d2 : d3;
            mma_bf16(dg, aF[4*kt], aF[4*kt+1], aF[4*kt+2], aF[4*kt+3], b0, b1);
        }
        float s0 = (d0[0] + d1[0]) + (d2[0] + d3[0]);   // D[lg][0]   (valid on lt==0)
        float s2 = (d0[2] + d1[2]) + (d2[2] + d3[2]);   // D[lg+8][0] (valid on lt==0)
        float v1 = tanha(s0 + px[step * HID + m1]);
        float v2 = tanha(s2 + px[step * HID + m1 + 8]);
        float v1n = __shfl_down_sync(0xffffffffu, v1, 4);
        float v2n = __shfl_down_sync(0xffffffffu, v2, 4);
        if (lt == 0 && (lg & 1) == 0) {
            hb[((step + 1) & 1) * 64 + w * 4 + (lg >> 1)] =
                pack2u(bf2u(v1, v1n), bf2u(v2, v2n));
        }
        u32 m = zmask[step];
        if (lt == 0) {
            if (m) {
#pragma unroll
                for (int n = 0; n < NNUM; n++)
                    if ((m >> n) & 1u) {
                        g_zz[n * HID + m1] = v1;
                        g_zz[n * HID + m1 + 8] = v2;
                    }
            }
            if (step == QLEN - 1) { g_q[m1] = v1; g_q[m1 + 8] = v2; }
        }
        __syncthreads();
    }
}

// ============================================================
// k_sel: single block, 512 threads — pivots + selector chain.
// ============================================================
__global__ void __launch_bounds__(512, 1)
k_sel(const int* __restrict__ nums_g, const float* __restrict__ Wop,
      const float* __restrict__ Wcol, const float* __restrict__ Whist,
      const float* __restrict__ opemb, const float* __restrict__ colemb,
      const float* __restrict__ Uv)
{
    __shared__ float zz[NNUM * HID];
    __shared__ float qpl[HID];
    __shared__ float hh[HID];
    __shared__ float uop[HID], ucol[HID], v3[HID], topo[HID], topc[HID];
    __shared__ float red[64];
    __shared__ float aop_s[16], acol_s[16];
    __shared__ float snum[NNUM];

    int tid  = threadIdx.x;
    int r    = tid >> 1, kh = tid & 1;
    int lane = tid & 31, wrp = tid >> 5;

    if (tid < NNUM) snum[tid] = (float)nums_g[tid];
    if (tid < HID)  { hh[tid] = 0.f; qpl[tid] = g_q[tid]; }
    for (int q = tid; q < NNUM * HID; q += 512) zz[q] = g_zz[q];
    __syncthreads();

    // ---- pivots ----
    {
        int p = wrp >> 3, n = wrp & 7;
        float s = 0.f;
#pragma unroll
        for (int j = 0; j < HID / 32; j++)
            s += zz[n * HID + j * 32 + lane] * Uv[p * HID + j * 32 + lane];
#pragma unroll
        for (int o = 16; o; o >>= 1) s += __shfl_xor_sync(0xffffffffu, s, o);
        if (lane == 0) red[p * 8 + n] = s;
    }
    __syncthreads();
    if (tid == 0) {
#pragma unroll
        for (int p = 0; p < 2; p++) {
            float m = -1e30f;
            for (int n = 0; n < 8; n++) m = fmaxf(m, red[p * 8 + n]);
            float den = 0.f, num = 0.f;
            for (int n = 0; n < 8; n++) {
                float e = expf(red[p * 8 + n] - m);
                den += e; num += e * snum[n];
            }
            g_piv[p] = num / den;
        }
    }

    // ---- timestep-invariant halves ----
    {
        const float4* q4 = (const float4*)(qpl + kh * 128);
        const float4* a4 = (const float4*)(Wop  + r * 512 + kh * 128);
        const float4* b4 = (const float4*)(Wcol + r * 512 + kh * 128);
        float s1 = 0.f, s2 = 0.f;
#pragma unroll
        for (int q = 0; q < 32; q++) {
            float4 h4 = q4[q];
            s1 += dot4(a4[q], h4);
            s2 += dot4(b4[q], h4);
        }
        s1 += __shfl_xor_sync(0xffffffffu, s1, 1);
        s2 += __shfl_xor_sync(0xffffffffu, s2, 1);
        if (kh == 0) { uop[r] = s1; ucol[r] = s2; }
    }
    __syncthreads();

    // ---- selector chain ----
    for (int t = 0; t < TSTEPS; t++) {
        {
            const float4* h4p = (const float4*)(hh + kh * 128);
            const float4* a4 = (const float4*)(Wop   + r * 512 + 256 + kh * 128);
            const float4* b4 = (const float4*)(Wcol  + r * 512 + 256 + kh * 128);
            const float4* c4 = (const float4*)(Whist + r * 768 + 512 + kh * 128);
            float s1 = 0.f, s2 = 0.f, s3 = 0.f;
#pragma unroll
            for (int q = 0; q < 32; q++) {
                float4 h4 = h4p[q];
                s1 += dot4(a4[q], h4);
                s2 += dot4(b4[q], h4);
                s3 += dot4(c4[q], h4);
            }
            s1 += __shfl_xor_sync(0xffffffffu, s1, 1);
            s2 += __shfl_xor_sync(0xffffffffu, s2, 1);
            s3 += __shfl_xor_sync(0xffffffffu, s3, 1);
            if (kh == 0) {
                topo[r] = tanha(uop[r] + s1);
                topc[r] = tanha(ucol[r] + s2);
                v3[r]   = s3;
            }
        }
        __syncthreads();
        if (wrp < NOPS) {
            float s = 0.f;
#pragma unroll
            for (int j = 0; j < HID / 32; j++)
                s += opemb[wrp * HID + j * 32 + lane] * topo[j * 32 + lane];
#pragma unroll
            for (int o = 16; o; o >>= 1) s += __shfl_xor_sync(0xffffffffu, s, o);
            if (lane == 0) red[wrp] = s;
        }
        {
            float s = 0.f;
#pragma unroll
            for (int j = 0; j < HID / 32; j++)
                s += colemb[wrp * HID + j * 32 + lane] * topc[j * 32 + lane];
#pragma unroll
            for (int o = 16; o; o >>= 1) s += __shfl_xor_sync(0xffffffffu, s, o);
            if (lane == 0) red[32 + wrp] = s;
        }
        __syncthreads();
        if (tid == 0) {
            float m = -1e30f;
            for (int o = 0; o < NOPS; o++) m = fmaxf(m, red[o]);
            float den = 0.f, e[NOPS];
            for (int o = 0; o < NOPS; o++) { e[o] = expf(red[o] - m); den += e[o]; }
            for (int o = 0; o < NOPS; o++) {
                float a = e[o] / den; aop_s[o] = a; g_aop[t * NOPS + o] = a;
            }
        }
        if (tid == 32) {
            float m = -1e30f;
            for (int c = 0; c < NCOLS; c++) m = fmaxf(m, red[32 + c]);
            float den = 0.f, e[NCOLS];
            for (int c = 0; c < NCOLS; c++) { e[c] = expf(red[32 + c] - m); den += e[c]; }
            for (int c = 0; c < NCOLS; c++) {
                float a = e[c] / den; acol_s[c] = a; g_acol[t * NCOLS + c] = a;
            }
        }
        __syncthreads();
        if (tid < HID) {
            float a = v3[tid];
#pragma unroll
            for (int o = 0; o < NOPS; o++)  a += g_M1[tid * NOPS + o] * aop_s[o];
#pragma unroll
            for (int c = 0; c < NCOLS; c++) a += g_M2[tid * NCOLS + c] * acol_s[c];
            hh[tid] = tanha(a);
        }
        __syncthreads();
    }
}

// ============================================================
// k_table: fused table pass + final reduction (last-block-done)
// ============================================================
#define K3T 256
__global__ void __launch_bounds__(K3T, 4)
k_table(const float* __restrict__ table, float* __restrict__ out, long rows)
{
    __shared__ ull   cf2[TSTEPS * NCOLS];
    __shared__ float cAnd[TSTEPS], cOr[TSTEPS], cRst[TSTEPS], cPass[TSTEPS];
    __shared__ float lkv[NCOLS];
    __shared__ float spv[2];
    __shared__ float wred[8 * 7];
    __shared__ int   sdone;
    __shared__ double sredd[7];

    int tid = threadIdx.x;
    if (tid < TSTEPS * NCOLS) {
        int t = tid >> 4, c = tid & 15;
        float ac = g_acol[t * NCOLS + c];
        cf2[tid] = pack2(g_aop[t * NOPS + 3] * ac, g_aop[t * NOPS + 4] * ac);
    } else if (tid < 64 + TSTEPS) {
        int t = tid - 64;
        cAnd[t]  = g_aop[t * NOPS + 5];
        cOr[t]   = g_aop[t * NOPS + 6];
        cRst[t]  = g_aop[t * NOPS + 8];
        cPass[t] = g_aop[t * NOPS + 0] + g_aop[t * NOPS + 1]
                 + g_aop[t * NOPS + 2] + g_aop[t * NOPS + 7];
    } else if (tid >= 96 && tid < 96 + NCOLS) {
        lkv[tid - 96] = g_aop[3 * NOPS + 7] * g_acol[3 * NCOLS + (tid - 96)];
    } else if (tid == 112) {
        spv[0] = g_piv[0]; spv[1] = g_piv[1];
    }
    __syncthreads();
    float lp = spv[0], gp = spv[1];
    int lane = tid & 31;
    float lkc = lkv[lane & 15];

    float accA = 0.f, aW0 = 0.f, aW1 = 0.f, aW2 = 0.f;
    float aC0 = 0.f, aC1 = 0.f, aC2 = 0.f;

    long stride = (long)gridDim.x * K3T;
    for (long base = (long)blockIdx.x * K3T; base < rows; base += stride) {
        long r = base + tid;
        float p1 = 0.f;
        if (r < rows) {
            const float4* tp = (const float4*)(table + r * NCOLS);
            float4 v0 = __ldcg(tp + 0), v1 = __ldcg(tp + 1);
            float4 v2 = __ldcg(tp + 2), v3r = __ldcg(tp + 3);
            float tv[16] = { v0.x, v0.y, v0.z, v0.w,  v1.x, v1.y, v1.z, v1.w,
                             v2.x, v2.y, v2.z, v2.w,  v3r.x, v3r.y, v3r.z, v3r.w };
            float rowsum = 0.f;
            ull acc0 = 0ull, acc1 = 0ull, acc2 = 0ull, acc3 = 0ull;
#pragma unroll
            for (int c = 0; c < 16; c++) {
                float v = tv[c];
                rowsum += v;
                float sg = fmaf(0.5f, tanha(0.5f * (v - gp)), 0.5f);
                float sl = fmaf(-0.5f, tanha(0.5f * (v - lp)), 0.5f);
                ull x = pack2(sg, sl);
                fma2(acc0, x, cf2[c]);
                fma2(acc1, x, cf2[16 + c]);
                fma2(acc2, x, cf2[32 + c]);
                fma2(acc3, x, cf2[48 + c]);
            }
            float2 d0 = unpack2(acc0), d1 = unpack2(acc1);
            float2 d2 = unpack2(acc2), d3 = unpack2(acc3);
            float d[4] = { d0.x + d0.y, d1.x + d1.y, d2.x + d2.y, d3.x + d3.y };
            accA += rowsum;
            float q1 = 1.f, q2 = 1.f;
#pragma unroll
            for (int t = 0; t < 4; t++) {
                float rs = d[t] + cAnd[t] * fminf(q1, q2)
                         + cOr[t] * fmaxf(q1, q2) + cRst[t] + cPass[t] * q1;
                if (t == 0) { aW0 += rs * rowsum; aC0 += rs; }
                else if (t == 1) { aW1 += rs * rowsum; aC1 += rs; }
                else if (t == 2) { aW2 += rs * rowsum; aC2 += rs; }
                q2 = q1; q1 = rs;
            }
            p1 = q1;
        }
        long rbase = base + (long)(tid & ~31);
        float* op = out + 1 + rbase * NCOLS;
#pragma unroll
        for (int m = 0; m < 16; m++) {
            int srcl = 2 * m + (lane >> 4);
            float v = __shfl_sync(0xffffffffu, p1, srcl);
            if (rbase + srcl < rows) op[m * 32 + lane] = v * lkc;
        }
    }

    float vals[7] = { accA, aW0, aW1, aW2, aC0, aC1, aC2 };
#pragma unroll
    for (int kk = 0; kk < 7; kk++) {
        float v = vals[kk];
#pragma unroll
        for (int o = 16; o; o >>= 1) v += __shfl_xor_sync(0xffffffffu, v, o);
        if ((tid & 31) == 0) wred[(tid >> 5) * 7 + kk] = v;
    }
    __syncthreads();
    if (tid < 7) {
        float s = 0.f;
        for (int wi = 0; wi < 8; wi++) s += wred[wi * 7 + tid];
        g_part[blockIdx.x * 8 + tid] = s;
    }
    __threadfence();
    __syncthreads();
    if (tid == 0) sdone = (atomicAdd(&g_ctr, 1u) == (u32)gridDim.x - 1u) ? 1 : 0;
    __syncthreads();
    if (!sdone) return;

    if (tid < 224) {
        int j = tid >> 5, ln = tid & 31;
        double s = 0.0;
        for (int b = ln; b < NBLK; b += 32) s += (double)g_part[b * 8 + j];
#pragma unroll
        for (int o = 16; o; o >>= 1) s += __shfl_xor_sync(0xffffffffu, s, o);
        if (ln == 0) sredd[j] = s;
    }
    __syncthreads();
    if (tid == 0) {
        double A   = sredd[0];
        double SW0 = sredd[1], SW1 = sredd[2], SW2 = sredd[3];
        double SC0 = sredd[4], SC1 = sredd[5], SC2 = sredd[6];
        const float* a0 = g_aop;
        const float* a1 = g_aop + NOPS;
        const float* a2 = g_aop + 2 * NOPS;
        const float* a3 = g_aop + 3 * NOPS;
        double s0 = (double)a0[0] * A   + (double)a0[1] * (double)rows;
        double s1 = (double)a1[0] * SW0 + (double)a1[1] * SC0 + (double)a1[2] * (0.0 - s0);
        double s2 = (double)a2[0] * SW1 + (double)a2[1] * SC1 + (double)a2[2] * (0.0 - s1);
        double s3 = (double)a3[0] * SW2 + (double)a3[1] * SC2 + (double)a3[2] * (s0 - s2);
        out[0] = (float)s3;
        g_ctr = 0u;
    }
}

// ============================================================
extern "C" void kernel_launch(void* const* d_in, const int* in_sizes, int n_in,
                              void* d_out, int out_size)
{
    const int*   qids   = (const int*)d_in[0];
    const int*   nums   = (const int*)d_in[1];
    const int*   lwi    = (const int*)d_in[2];
    const float* table  = (const float*)d_in[3];
    const float* emb    = (const float*)d_in[4];
    const float* Wx     = (const float*)d_in[5];
    const float* Wh     = (const float*)d_in[6];
    const float* Wop    = (const float*)d_in[7];
    const float* opemb  = (const float*)d_in[8];
    const float* Wcol   = (const float*)d_in[9];
    const float* colemb = (const float*)d_in[10];
    const float* Whist  = (const float*)d_in[11];
    const float* Uv     = (const float*)d_in[12];
    float* out = (float*)d_out;
    long rows = (long)in_sizes[3] / NCOLS;

    cudaFuncSetAttribute(k_rnn, cudaFuncAttributeMaxDynamicSharedMemorySize, R_SMEM);

    k_prep<<<QLEN + NOPS + NCOLS, 512>>>(qids, emb, Wx, Whist, opemb, colemb);
    k_rnn<<<1, RNT, R_SMEM>>>(lwi, Wh);
    k_sel<<<1, 512>>>(nums, Wop, Wcol, Whist, opemb, colemb, Uv);
    k_table<<<NBLK, K3T>>>(table, out, rows);
}

// round 13
// speedup vs baseline: 1.8225x; 1.0751x over previous
#include <cuda_runtime.h>
#include <cuda_bf16.h>

#define HID    256
#define QLEN   64
#define NOPS   9
#define NCOLS  16
#define TSTEPS 4
#define NNUM   8
typedef unsigned long long ull;
typedef unsigned int u32;

// ops: SUM=0 COUNT=1 DIFF=2 GREATER=3 LESSER=4 AND=5 OR=6 ASSIGN=7 RESET=8

__device__ __forceinline__ void fma2(ull& acc, ull a, ull b) {
    asm("fma.rn.f32x2 %0, %1, %2, %0;" : "+l"(acc) : "l"(a), "l"(b));
}
__device__ __forceinline__ ull pack2(float lo, float hi) {
    ull u; asm("mov.b64 %0, {%1, %2};" : "=l"(u) : "f"(lo), "f"(hi)); return u;
}
__device__ __forceinline__ ull pack2u(u32 lo, u32 hi) {
    ull u; asm("mov.b64 %0, {%1, %2};" : "=l"(u) : "r"(lo), "r"(hi)); return u;
}
__device__ __forceinline__ float2 unpack2(ull u) {
    float2 f; asm("mov.b64 {%0, %1}, %2;" : "=f"(f.x), "=f"(f.y) : "l"(u)); return f;
}
__device__ __forceinline__ float tanha(float x) {
    float y; asm("tanh.approx.f32 %0, %1;" : "=f"(y) : "f"(x)); return y;
}
__device__ __forceinline__ u32 bf2u(float a, float b) {
    __nv_bfloat162 p = __floats2bfloat162_rn(a, b);
    return *(u32*)&p;
}
__device__ __forceinline__ float dot4(float4 a, float4 b) {
    return a.x * b.x + a.y * b.y + a.z * b.z + a.w * b.w;
}
__device__ __forceinline__ ull bfexp(u32 w) {       // packed bf16 pair -> packed f32 pair
    return pack2u(w << 16, w & 0xffff0000u);
}
// D(16x8) += A(16x16,bf16,row) * B(16x8,bf16,col); f32 accum
__device__ __forceinline__ void mma_bf16(float* d, u32 a0, u32 a1, u32 a2, u32 a3,
                                         u32 b0, u32 b1) {
    asm volatile(
        "mma.sync.aligned.m16n8k16.row.col.f32.bf16.bf16.f32 "
        "{%0,%1,%2,%3}, {%4,%5,%6,%7}, {%8,%9}, {%0,%1,%2,%3};"
        : "+f"(d[0]), "+f"(d[1]), "+f"(d[2]), "+f"(d[3])
        : "r"(a0), "r"(a1), "r"(a2), "r"(a3), "r"(b0), "r"(b1));
}

// ---------------- device-global scratch ----------------
#define NBLK 1184
__device__ float  g_px[QLEN * HID];
__device__ float  g_M1[HID * NOPS];
__device__ float  g_M2[HID * NCOLS];
__device__ float  g_aop[TSTEPS * NOPS];
__device__ float  g_acol[TSTEPS * NCOLS];
__device__ float  g_piv[2];
__device__ float  g_part[NBLK * 8];
__device__ u32    g_ctr;
__device__ u32    g_whf[64 * 512];        // Wh in mma A-fragment order, bf16 pairs
__device__ u32    g_wsel[5 * 32768];      // bf16 pairs: Wop1,Wop2,Wcol1,Wcol2,Whist2

// ============================================================
// k_prep: 89 + 64 + 160 = 313 blocks x 512 threads
//   b<89: px/M1/M2 GEMVs (split-K). b in [89,153): Wh fragment pack.
//   b>=153: selector weight chunks -> bf16.
// ============================================================
__global__ void k_prep(const int* __restrict__ qids, const float* __restrict__ emb,
                       const float* __restrict__ Wx, const float* __restrict__ Wh,
                       const float* __restrict__ Wop, const float* __restrict__ Wcol,
                       const float* __restrict__ Whist,
                       const float* __restrict__ opemb, const float* __restrict__ colemb)
{
    __shared__ float xs[HID];
    int b = blockIdx.x, tid = threadIdx.x;

    if (b >= 89 && b < 153) {
        int j_idx = b - 89;
        int kt = j_idx >> 2, j = j_idx & 3;
        int w = tid >> 5, lane = tid & 31, lg = lane >> 2, lt = lane & 3;
        int row = 16 * w + lg + ((j & 1) ? 8 : 0);
        int col = kt * 16 + 2 * lt + ((j >= 2) ? 8 : 0);
        float2 x = *(const float2*)(Wh + row * HID + col);
        g_whf[j_idx * 512 + tid] = bf2u(x.x, x.y);
        return;
    }
    if (b >= 153) {
        int cb = b - 153;
        int chunk = cb >> 5, blk = cb & 31;
        int idx = blk * 512 + tid;            // 0..16383 float4s per chunk
        int r = idx >> 6, f4 = idx & 63;
        const float* src;
        if (chunk == 0)      src = Wop   + r * 512 + f4 * 4;
        else if (chunk == 1) src = Wop   + r * 512 + 256 + f4 * 4;
        else if (chunk == 2) src = Wcol  + r * 512 + f4 * 4;
        else if (chunk == 3) src = Wcol  + r * 512 + 256 + f4 * 4;
        else                 src = Whist + r * 768 + 512 + f4 * 4;
        float4 v = *(const float4*)src;
        uint2 o = make_uint2(bf2u(v.x, v.y), bf2u(v.z, v.w));
        *(uint2*)(g_wsel + chunk * 32768 + r * 128 + f4 * 2) = o;
        return;
    }

    int i = tid >> 1, half = tid & 1;
    const float* wrow;
    float* dst;
    if (b < QLEN) {
        if (tid < HID) xs[tid] = emb[(long)qids[b] * HID + tid];
        wrow = Wx + i * HID + half * 128;
        dst  = g_px + b * HID + i;
    } else if (b < QLEN + NOPS) {
        int o = b - QLEN;
        if (tid < HID) xs[tid] = opemb[o * HID + tid];
        wrow = Whist + i * 768 + half * 128;
        dst  = g_M1 + i * NOPS + o;
    } else {
        int c = b - QLEN - NOPS;
        if (tid < HID) xs[tid] = colemb[c * HID + tid];
        wrow = Whist + i * 768 + 256 + half * 128;
        dst  = g_M2 + i * NCOLS + c;
    }
    __syncthreads();
    const float4* w4 = (const float4*)wrow;
    const float4* x4 = (const float4*)(xs + half * 128);
    float s0 = 0.f, s1 = 0.f;
#pragma unroll
    for (int q = 0; q < 32; q += 2) {
        s0 += dot4(w4[q], x4[q]);
        s1 += dot4(w4[q + 1], x4[q + 1]);
    }
    float s = s0 + s1;
    s += __shfl_xor_sync(0xffffffffu, s, 1);
    if (half == 0) *dst = s;
}

// ============================================================
// k_core: single block, 512 threads.
// Phase 1: tensor-core RNN (mma.sync bf16, Wh frags pre-packed).
// Phase 2: pivots.  Phase 3: uop/ucol (bf16).  Phase 4: 4 selector steps (bf16).
// ============================================================
#define CNT 512

// dynamic smem byte offsets
#define CB_PX    0                    // 65536
#define CB_HB    65536                // 1024  (2 x 64 ull)
#define CB_ZM    66560                // 256
#define CB_SL    66816                // 32
#define CB_ZZ    66848                // 8192
#define CB_QPL   75040                // 1024
#define CB_HH    76064                // 1024
#define CB_UOP   77088
#define CB_UCOL  78112
#define CB_V3    79136
#define CB_TOPO  80160
#define CB_TOPC  81184
#define CB_RED   82208                // 256
#define CB_AOPS  82464                // 64
#define CB_ACOLS 82528                // 64
#define CB_SNUM  82592                // 32
#define C_SMEM   82624

__global__ void __launch_bounds__(CNT, 1)
k_core(const int* __restrict__ lwi_g, const int* __restrict__ nums_g,
       const float* __restrict__ opemb, const float* __restrict__ colemb,
       const float* __restrict__ Uv)
{
    extern __shared__ char smraw[];
    float* px    = (float*)(smraw + CB_PX);
    ull*   hb    = (ull*)(smraw + CB_HB);
    u32*  zmask  = (u32*)(smraw + CB_ZM);
    int*  slwi   = (int*)(smraw + CB_SL);
    float* zz    = (float*)(smraw + CB_ZZ);
    float* qpl   = (float*)(smraw + CB_QPL);
    float* hh    = (float*)(smraw + CB_HH);
    float* uop   = (float*)(smraw + CB_UOP);
    float* ucol  = (float*)(smraw + CB_UCOL);
    float* v3    = (float*)(smraw + CB_V3);
    float* topo  = (float*)(smraw + CB_TOPO);
    float* topc  = (float*)(smraw + CB_TOPC);
    float* red   = (float*)(smraw + CB_RED);
    float* aop_s = (float*)(smraw + CB_AOPS);
    float* acol_s= (float*)(smraw + CB_ACOLS);
    float* snum  = (float*)(smraw + CB_SNUM);

    int tid = threadIdx.x;
    int w = tid >> 5, lane = tid & 31, wrp = w;
    int lg = lane >> 2, lt = lane & 3;

    if (tid < NNUM) { slwi[tid] = lwi_g[tid]; snum[tid] = (float)nums_g[tid]; }
    if (tid < 64) hb[tid] = 0ull;
    if (tid < HID) hh[tid] = 0.f;
    {
        const float4* src = (const float4*)g_px;
        float4* dst = (float4*)px;
        for (int q = tid; q < QLEN * HID / 4; q += CNT) dst[q] = src[q];
    }
    // A-fragments, coalesced from pre-packed layout
    u32 aF[64];
#pragma unroll
    for (int q = 0; q < 64; q++) aF[q] = g_whf[q * 512 + tid];
    __syncthreads();
    if (tid < QLEN) {
        u32 m = 0;
#pragma unroll
        for (int n = 0; n < NNUM; n++)
            if (slwi[n] == tid) m |= (1u << n);
        zmask[tid] = m;
    }
    __syncthreads();

    // ---- Phase 1: RNN (64 steps) ----
    int m1 = 16 * w + lg;
    for (int step = 0; step < QLEN; step++) {
        const ull* hbc = hb + (step & 1) * 64;
        float d0[4] = {0.f,0.f,0.f,0.f}, d1[4] = {0.f,0.f,0.f,0.f};
        float d2[4] = {0.f,0.f,0.f,0.f}, d3[4] = {0.f,0.f,0.f,0.f};
#pragma unroll
        for (int kt = 0; kt < 16; kt++) {
            ull bb = hbc[kt * 4 + lt];
            u32 b0 = (u32)bb, b1 = (u32)(bb >> 32);
            float* dg = (kt & 3) == 0 ? d0 : (kt & 3) == 1 ? d1 : (kt & 3) == 2 ? d2 : d3;
            mma_bf16(dg, aF[4*kt], aF[4*kt+1], aF[4*kt+2], aF[4*kt+3], b0, b1);
        }
        float s0 = (d0[0] + d1[0]) + (d2[0] + d3[0]);
        float s2 = (d0[2] + d1[2]) + (d2[2] + d3[2]);
        float v1 = tanha(s0 + px[step * HID + m1]);
        float v2 = tanha(s2 + px[step * HID + m1 + 8]);
        float v1n = __shfl_down_sync(0xffffffffu, v1, 4);
        float v2n = __shfl_down_sync(0xffffffffu, v2, 4);
        if (lt == 0 && (lg & 1) == 0) {
            hb[((step + 1) & 1) * 64 + w * 4 + (lg >> 1)] =
                pack2u(bf2u(v1, v1n), bf2u(v2, v2n));
        }
        u32 m = zmask[step];
        if (lt == 0) {
            if (m) {
#pragma unroll
                for (int n = 0; n < NNUM; n++)
                    if ((m >> n) & 1u) {
                        zz[n * HID + m1] = v1;
                        zz[n * HID + m1 + 8] = v2;
                    }
            }
            if (step == QLEN - 1) { qpl[m1] = v1; qpl[m1 + 8] = v2; }
        }
        __syncthreads();
    }

    // ---- Phase 2: pivots ----
    {
        int p = wrp >> 3, n = wrp & 7;
        float s = 0.f;
#pragma unroll
        for (int j = 0; j < HID / 32; j++)
            s += zz[n * HID + j * 32 + lane] * Uv[p * HID + j * 32 + lane];
#pragma unroll
        for (int o = 16; o; o >>= 1) s += __shfl_xor_sync(0xffffffffu, s, o);
        if (lane == 0) red[p * 8 + n] = s;
    }
    __syncthreads();
    if (tid == 0) {
#pragma unroll
        for (int p = 0; p < 2; p++) {
            float m = -1e30f;
            for (int n = 0; n < 8; n++) m = fmaxf(m, red[p * 8 + n]);
            float den = 0.f, num = 0.f;
            for (int n = 0; n < 8; n++) {
                float e = expf(red[p * 8 + n] - m);
                den += e; num += e * snum[n];
            }
            g_piv[p] = num / den;
        }
    }

    // ---- Phase 3: uop/ucol from bf16 chunks ----
    int r = tid >> 1, kh = tid & 1;
    {
        const uint4* wa4 = (const uint4*)(g_wsel + 0 * 32768) + r * 32 + kh * 16;
        const uint4* wb4 = (const uint4*)(g_wsel + 2 * 32768) + r * 32 + kh * 16;
        const ulonglong2* q2 = (const ulonglong2*)(qpl + kh * 128);
        ull a1 = 0ull, a2 = 0ull, b1a = 0ull, b2 = 0ull;
#pragma unroll
        for (int i = 0; i < 16; i++) {
            uint4 wa = wa4[i], wb = wb4[i];
            ulonglong2 h2a = q2[2*i], h2b = q2[2*i + 1];
            fma2(a1, bfexp(wa.x), h2a.x); fma2(a2, bfexp(wa.y), h2a.y);
            fma2(a1, bfexp(wa.z), h2b.x); fma2(a2, bfexp(wa.w), h2b.y);
            fma2(b1a, bfexp(wb.x), h2a.x); fma2(b2, bfexp(wb.y), h2a.y);
            fma2(b1a, bfexp(wb.z), h2b.x); fma2(b2, bfexp(wb.w), h2b.y);
        }
        float2 fa = unpack2(a1), fb = unpack2(a2);
        float2 fc = unpack2(b1a), fd = unpack2(b2);
        float s1 = (fa.x + fa.y) + (fb.x + fb.y);
        float s2 = (fc.x + fc.y) + (fd.x + fd.y);
        s1 += __shfl_xor_sync(0xffffffffu, s1, 1);
        s2 += __shfl_xor_sync(0xffffffffu, s2, 1);
        if (kh == 0) { uop[r] = s1; ucol[r] = s2; }
    }
    __syncthreads();

    // ---- Phase 4: selector chain (bf16 GEMVs) ----
    for (int t = 0; t < TSTEPS; t++) {
        {
            const uint4* a4 = (const uint4*)(g_wsel + 1 * 32768) + r * 32 + kh * 16;
            const uint4* b4 = (const uint4*)(g_wsel + 3 * 32768) + r * 32 + kh * 16;
            const uint4* c4 = (const uint4*)(g_wsel + 4 * 32768) + r * 32 + kh * 16;
            const ulonglong2* h2 = (const ulonglong2*)(hh + kh * 128);
            ull s1a = 0ull, s1b = 0ull, s2a = 0ull, s2b = 0ull, s3a = 0ull, s3b = 0ull;
#pragma unroll
            for (int i = 0; i < 16; i++) {
                uint4 wa = a4[i], wb = b4[i], wc = c4[i];
                ulonglong2 h2a = h2[2*i], h2b = h2[2*i + 1];
                fma2(s1a, bfexp(wa.x), h2a.x); fma2(s1b, bfexp(wa.y), h2a.y);
                fma2(s1a, bfexp(wa.z), h2b.x); fma2(s1b, bfexp(wa.w), h2b.y);
                fma2(s2a, bfexp(wb.x), h2a.x); fma2(s2b, bfexp(wb.y), h2a.y);
                fma2(s2a, bfexp(wb.z), h2b.x); fma2(s2b, bfexp(wb.w), h2b.y);
                fma2(s3a, bfexp(wc.x), h2a.x); fma2(s3b, bfexp(wc.y), h2a.y);
                fma2(s3a, bfexp(wc.z), h2b.x); fma2(s3b, bfexp(wc.w), h2b.y);
            }
            float2 f1 = unpack2(s1a), f1b = unpack2(s1b);
            float2 f2 = unpack2(s2a), f2b = unpack2(s2b);
            float2 f3 = unpack2(s3a), f3b = unpack2(s3b);
            float s1 = (f1.x + f1.y) + (f1b.x + f1b.y);
            float s2 = (f2.x + f2.y) + (f2b.x + f2b.y);
            float s3 = (f3.x + f3.y) + (f3b.x + f3b.y);
            s1 += __shfl_xor_sync(0xffffffffu, s1, 1);
            s2 += __shfl_xor_sync(0xffffffffu, s2, 1);
            s3 += __shfl_xor_sync(0xffffffffu, s3, 1);
            if (kh == 0) {
                topo[r] = tanha(uop[r] + s1);
                topc[r] = tanha(ucol[r] + s2);
                v3[r]   = s3;
            }
        }
        __syncthreads();
        if (wrp < NOPS) {
            float s = 0.f;
#pragma unroll
            for (int j = 0; j < HID / 32; j++)
                s += opemb[wrp * HID + j * 32 + lane] * topo[j * 32 + lane];
#pragma unroll
            for (int o = 16; o; o >>= 1) s += __shfl_xor_sync(0xffffffffu, s, o);
            if (lane == 0) red[wrp] = s;
        }
        {
            float s = 0.f;
#pragma unroll
            for (int j = 0; j < HID / 32; j++)
                s += colemb[wrp * HID + j * 32 + lane] * topc[j * 32 + lane];
#pragma unroll
            for (int o = 16; o; o >>= 1) s += __shfl_xor_sync(0xffffffffu, s, o);
            if (lane == 0) red[32 + wrp] = s;
        }
        __syncthreads();
        if (tid == 0) {
            float m = -1e30f;
            for (int o = 0; o < NOPS; o++) m = fmaxf(m, red[o]);
            float den = 0.f, e[NOPS];
            for (int o = 0; o < NOPS; o++) { e[o] = expf(red[o] - m); den += e[o]; }
            for (int o = 0; o < NOPS; o++) {
                float a = e[o] / den; aop_s[o] = a; g_aop[t * NOPS + o] = a;
            }
        }
        if (tid == 32) {
            float m = -1e30f;
            for (int c = 0; c < NCOLS; c++) m = fmaxf(m, red[32 + c]);
            float den = 0.f, e[NCOLS];
            for (int c = 0; c < NCOLS; c++) { e[c] = expf(red[32 + c] - m); den += e[c]; }
            for (int c = 0; c < NCOLS; c++) {
                float a = e[c] / den; acol_s[c] = a; g_acol[t * NCOLS + c] = a;
            }
        }
        __syncthreads();
        if (tid < HID) {
            float a = v3[tid];
#pragma unroll
            for (int o = 0; o < NOPS; o++)  a += g_M1[tid * NOPS + o] * aop_s[o];
#pragma unroll
            for (int c = 0; c < NCOLS; c++) a += g_M2[tid * NCOLS + c] * acol_s[c];
            hh[tid] = tanha(a);
        }
        __syncthreads();
    }
}

// ============================================================
// k_table: fused table pass + final reduction (last-block-done)
// ============================================================
#define K3T 256
__global__ void __launch_bounds__(K3T, 4)
k_table(const float* __restrict__ table, float* __restrict__ out, long rows)
{
    __shared__ ull   cf2[TSTEPS * NCOLS];
    __shared__ float cAnd[TSTEPS], cOr[TSTEPS], cRst[TSTEPS], cPass[TSTEPS];
    __shared__ float lkv[NCOLS];
    __shared__ float spv[2];
    __shared__ float wred[8 * 7];
    __shared__ int   sdone;
    __shared__ double sredd[7];

    int tid = threadIdx.x;
    if (tid < TSTEPS * NCOLS) {
        int t = tid >> 4, c = tid & 15;
        float ac = g_acol[t * NCOLS + c];
        cf2[tid] = pack2(g_aop[t * NOPS + 3] * ac, g_aop[t * NOPS + 4] * ac);
    } else if (tid < 64 + TSTEPS) {
        int t = tid - 64;
        cAnd[t]  = g_aop[t * NOPS + 5];
        cOr[t]   = g_aop[t * NOPS + 6];
        cRst[t]  = g_aop[t * NOPS + 8];
        cPass[t] = g_aop[t * NOPS + 0] + g_aop[t * NOPS + 1]
                 + g_aop[t * NOPS + 2] + g_aop[t * NOPS + 7];
    } else if (tid >= 96 && tid < 96 + NCOLS) {
        lkv[tid - 96] = g_aop[3 * NOPS + 7] * g_acol[3 * NCOLS + (tid - 96)];
    } else if (tid == 112) {
        spv[0] = g_piv[0]; spv[1] = g_piv[1];
    }
    __syncthreads();
    float lp = spv[0], gp = spv[1];
    int lane = tid & 31;
    float lkc = lkv[lane & 15];

    float accA = 0.f, aW0 = 0.f, aW1 = 0.f, aW2 = 0.f;
    float aC0 = 0.f, aC1 = 0.f, aC2 = 0.f;

    long stride = (long)gridDim.x * K3T;
    for (long base = (long)blockIdx.x * K3T; base < rows; base += stride) {
        long r = base + tid;
        float p1 = 0.f;
        if (r < rows) {
            const float4* tp = (const float4*)(table + r * NCOLS);
            float4 v0 = __ldcg(tp + 0), v1 = __ldcg(tp + 1);
            float4 v2 = __ldcg(tp + 2), v3r = __ldcg(tp + 3);
            float tv[16] = { v0.x, v0.y, v0.z, v0.w,  v1.x, v1.y, v1.z, v1.w,
                             v2.x, v2.y, v2.z, v2.w,  v3r.x, v3r.y, v3r.z, v3r.w };
            float rowsum = 0.f;
            ull acc0 = 0ull, acc1 = 0ull, acc2 = 0ull, acc3 = 0ull;
#pragma unroll
            for (int c = 0; c < 16; c++) {
                float v = tv[c];
                rowsum += v;
                float sg = fmaf(0.5f, tanha(0.5f * (v - gp)), 0.5f);
                float sl = fmaf(-0.5f, tanha(0.5f * (v - lp)), 0.5f);
                ull x = pack2(sg, sl);
                fma2(acc0, x, cf2[c]);
                fma2(acc1, x, cf2[16 + c]);
                fma2(acc2, x, cf2[32 + c]);
                fma2(acc3, x, cf2[48 + c]);
            }
            float2 d0 = unpack2(acc0), d1 = unpack2(acc1);
            float2 d2 = unpack2(acc2), d3 = unpack2(acc3);
            float d[4] = { d0.x + d0.y, d1.x + d1.y, d2.x + d2.y, d3.x + d3.y };
            accA += rowsum;
            float q1 = 1.f, q2 = 1.f;
#pragma unroll
            for (int t = 0; t < 4; t++) {
                float rs = d[t] + cAnd[t] * fminf(q1, q2)
                         + cOr[t] * fmaxf(q1, q2) + cRst[t] + cPass[t] * q1;
                if (t == 0) { aW0 += rs * rowsum; aC0 += rs; }
                else if (t == 1) { aW1 += rs * rowsum; aC1 += rs; }
                else if (t == 2) { aW2 += rs * rowsum; aC2 += rs; }
                q2 = q1; q1 = rs;
            }
            p1 = q1;
        }
        long rbase = base + (long)(tid & ~31);
        float* op = out + 1 + rbase * NCOLS;
#pragma unroll
        for (int m = 0; m < 16; m++) {
            int srcl = 2 * m + (lane >> 4);
            float v = __shfl_sync(0xffffffffu, p1, srcl);
            if (rbase + srcl < rows) op[m * 32 + lane] = v * lkc;
        }
    }

    float vals[7] = { accA, aW0, aW1, aW2, aC0, aC1, aC2 };
#pragma unroll
    for (int kk = 0; kk < 7; kk++) {
        float v = vals[kk];
#pragma unroll
        for (int o = 16; o; o >>= 1) v += __shfl_xor_sync(0xffffffffu, v, o);
        if ((tid & 31) == 0) wred[(tid >> 5) * 7 + kk] = v;
    }
    __syncthreads();
    if (tid < 7) {
        float s = 0.f;
        for (int wi = 0; wi < 8; wi++) s += wred[wi * 7 + tid];
        g_part[blockIdx.x * 8 + tid] = s;
    }
    __threadfence();
    __syncthreads();
    if (tid == 0) sdone = (atomicAdd(&g_ctr, 1u) == (u32)gridDim.x - 1u) ? 1 : 0;
    __syncthreads();
    if (!sdone) return;

    if (tid < 224) {
        int j = tid >> 5, ln = tid & 31;
        double s = 0.0;
        for (int b = ln; b < NBLK; b += 32) s += (double)g_part[b * 8 + j];
#pragma unroll
        for (int o = 16; o; o >>= 1) s += __shfl_xor_sync(0xffffffffu, s, o);
        if (ln == 0) sredd[j] = s;
    }
    __syncthreads();
    if (tid == 0) {
        double A   = sredd[0];
        double SW0 = sredd[1], SW1 = sredd[2], SW2 = sredd[3];
        double SC0 = sredd[4], SC1 = sredd[5], SC2 = sredd[6];
        const float* a0 = g_aop;
        const float* a1 = g_aop + NOPS;
        const float* a2 = g_aop + 2 * NOPS;
        const float* a3 = g_aop + 3 * NOPS;
        double s0 = (double)a0[0] * A   + (double)a0[1] * (double)rows;
        double s1 = (double)a1[0] * SW0 + (double)a1[1] * SC0 + (double)a1[2] * (0.0 - s0);
        double s2 = (double)a2[0] * SW1 + (double)a2[1] * SC1 + (double)a2[2] * (0.0 - s1);
        double s3 = (double)a3[0] * SW2 + (double)a3[1] * SC2 + (double)a3[2] * (s0 - s2);
        out[0] = (float)s3;
        g_ctr = 0u;
    }
}

// ============================================================
extern "C" void kernel_launch(void* const* d_in, const int* in_sizes, int n_in,
                              void* d_out, int out_size)
{
    const int*   qids   = (const int*)d_in[0];
    const int*   nums   = (const int*)d_in[1];
    const int*   lwi    = (const int*)d_in[2];
    const float* table  = (const float*)d_in[3];
    const float* emb    = (const float*)d_in[4];
    const float* Wx     = (const float*)d_in[5];
    const float* Wh     = (const float*)d_in[6];
    const float* Wop    = (const float*)d_in[7];
    const float* opemb  = (const float*)d_in[8];
    const float* Wcol   = (const float*)d_in[9];
    const float* colemb = (const float*)d_in[10];
    const float* Whist  = (const float*)d_in[11];
    const float* Uv     = (const float*)d_in[12];
    float* out = (float*)d_out;
    long rows = (long)in_sizes[3] / NCOLS;

    cudaFuncSetAttribute(k_core, cudaFuncAttributeMaxDynamicSharedMemorySize, C_SMEM);

    k_prep<<<313, 512>>>(qids, emb, Wx, Wh, Wop, Wcol, Whist, opemb, colemb);
    k_core<<<1, CNT, C_SMEM>>>(lwi, nums, opemb, colemb, Uv);
    k_table<<<NBLK, K3T>>>(table, out, rows);
}

// round 14
// speedup vs baseline: 2.5496x; 1.3990x over previous
#include <cuda_runtime.h>
#include <cuda_bf16.h>

#define HID    256
#define QLEN   64
#define NOPS   9
#define NCOLS  16
#define TSTEPS 4
#define NNUM   8
typedef unsigned long long ull;
typedef unsigned int u32;

// ops: SUM=0 COUNT=1 DIFF=2 GREATER=3 LESSER=4 AND=5 OR=6 ASSIGN=7 RESET=8

__device__ __forceinline__ void fma2(ull& acc, ull a, ull b) {
    asm("fma.rn.f32x2 %0, %1, %2, %0;" : "+l"(acc) : "l"(a), "l"(b));
}
__device__ __forceinline__ ull pack2(float lo, float hi) {
    ull u; asm("mov.b64 %0, {%1, %2};" : "=l"(u) : "f"(lo), "f"(hi)); return u;
}
__device__ __forceinline__ ull pack2u(u32 lo, u32 hi) {
    ull u; asm("mov.b64 %0, {%1, %2};" : "=l"(u) : "r"(lo), "r"(hi)); return u;
}
__device__ __forceinline__ float2 unpack2(ull u) {
    float2 f; asm("mov.b64 {%0, %1}, %2;" : "=f"(f.x), "=f"(f.y) : "l"(u)); return f;
}
__device__ __forceinline__ float tanha(float x) {
    float y; asm("tanh.approx.f32 %0, %1;" : "=f"(y) : "f"(x)); return y;
}
__device__ __forceinline__ u32 bf2u(float a, float b) {
    __nv_bfloat162 p = __floats2bfloat162_rn(a, b);
    return *(u32*)&p;
}
__device__ __forceinline__ float dot4(float4 a, float4 b) {
    return a.x * b.x + a.y * b.y + a.z * b.z + a.w * b.w;
}
__device__ __forceinline__ ull bfexp(u32 w) {       // packed bf16 pair -> packed f32 pair
    return pack2u(w << 16, w & 0xffff0000u);
}
// D(16x8) += A(16x16,bf16,row) * B(16x8,bf16,col); f32 accum
__device__ __forceinline__ void mma_bf16(float* d, u32 a0, u32 a1, u32 a2, u32 a3,
                                         u32 b0, u32 b1) {
    asm volatile(
        "mma.sync.aligned.m16n8k16.row.col.f32.bf16.bf16.f32 "
        "{%0,%1,%2,%3}, {%4,%5,%6,%7}, {%8,%9}, {%0,%1,%2,%3};"
        : "+f"(d[0]), "+f"(d[1]), "+f"(d[2]), "+f"(d[3])
        : "r"(a0), "r"(a1), "r"(a2), "r"(a3), "r"(b0), "r"(b1));
}

// ---------------- device-global scratch ----------------
#define NBLK 1184
__device__ float  g_px[QLEN * HID];
__device__ float  g_M1[HID * NOPS];
__device__ float  g_M2[HID * NCOLS];
__device__ float  g_aop[TSTEPS * NOPS];
__device__ float  g_acol[TSTEPS * NCOLS];
__device__ float  g_piv[2];
__device__ float  g_part[NBLK * 8];
__device__ u32    g_ctr;
__device__ u32    g_whf[64 * 512];        // Wh in mma A-fragment order, bf16 pairs
__device__ uint4  g_wsel[5 * 8192];       // TRANSPOSED bf16 chunks: [chunk][i*512+tid]

// ============================================================
// k_prep: 89 + 64 + 80 = 233 blocks x 512 threads
//   b<89: px/M1/M2 GEMVs. b in [89,153): Wh fragment pack.
//   b in [153,233): selector weights -> bf16, consumer-transposed layout.
// ============================================================
__global__ void k_prep(const int* __restrict__ qids, const float* __restrict__ emb,
                       const float* __restrict__ Wx, const float* __restrict__ Wh,
                       const float* __restrict__ Wop, const float* __restrict__ Wcol,
                       const float* __restrict__ Whist,
                       const float* __restrict__ opemb, const float* __restrict__ colemb)
{
    __shared__ float xs[HID];
    int b = blockIdx.x, tid = threadIdx.x;

    if (b >= 89 && b < 153) {
        int j_idx = b - 89;
        int kt = j_idx >> 2, j = j_idx & 3;
        int w = tid >> 5, lane = tid & 31, lg = lane >> 2, lt = lane & 3;
        int row = 16 * w + lg + ((j & 1) ? 8 : 0);
        int col = kt * 16 + 2 * lt + ((j >= 2) ? 8 : 0);
        float2 x = *(const float2*)(Wh + row * HID + col);
        g_whf[j_idx * 512 + tid] = bf2u(x.x, x.y);
        return;
    }
    if (b >= 153) {
        int b2 = b - 153;
        int chunk = b2 >> 4, i = b2 & 15;
        int r = tid >> 1, kh = tid & 1;
        const float* src;
        if (chunk == 0)      src = Wop   + r * 512;
        else if (chunk == 1) src = Wop   + r * 512 + 256;
        else if (chunk == 2) src = Wcol  + r * 512;
        else if (chunk == 3) src = Wcol  + r * 512 + 256;
        else                 src = Whist + r * 768 + 512;
        int cb = kh * 128 + i * 8;
        float4 v0 = *(const float4*)(src + cb);
        float4 v1 = *(const float4*)(src + cb + 4);
        g_wsel[chunk * 8192 + i * 512 + tid] =
            make_uint4(bf2u(v0.x, v0.y), bf2u(v0.z, v0.w),
                       bf2u(v1.x, v1.y), bf2u(v1.z, v1.w));
        return;
    }

    int i = tid >> 1, half = tid & 1;
    const float* wrow;
    float* dst;
    if (b < QLEN) {
        if (tid < HID) xs[tid] = emb[(long)qids[b] * HID + tid];
        wrow = Wx + i * HID + half * 128;
        dst  = g_px + b * HID + i;
    } else if (b < QLEN + NOPS) {
        int o = b - QLEN;
        if (tid < HID) xs[tid] = opemb[o * HID + tid];
        wrow = Whist + i * 768 + half * 128;
        dst  = g_M1 + i * NOPS + o;
    } else {
        int c = b - QLEN - NOPS;
        if (tid < HID) xs[tid] = colemb[c * HID + tid];
        wrow = Whist + i * 768 + 256 + half * 128;
        dst  = g_M2 + i * NCOLS + c;
    }
    __syncthreads();
    const float4* w4 = (const float4*)wrow;
    const float4* x4 = (const float4*)(xs + half * 128);
    float s0 = 0.f, s1 = 0.f;
#pragma unroll
    for (int q = 0; q < 32; q += 2) {
        s0 += dot4(w4[q], x4[q]);
        s1 += dot4(w4[q + 1], x4[q + 1]);
    }
    float s = s0 + s1;
    s += __shfl_xor_sync(0xffffffffu, s, 1);
    if (half == 0) *dst = s;
}

// ============================================================
// k_core: single block, 512 threads.
// Phase 1: mma.sync RNN.  Phase 2: pivots.  Phase 3: uop/ucol.
// Phase 4: 4 selector steps.  All weight streams coalesced (transposed bf16).
// ============================================================
#define CNT 512

// dynamic smem byte offsets
#define CB_PX    0                    // 65536
#define CB_HB    65536                // 1024
#define CB_ZM    66560                // 256
#define CB_SL    66816                // 32
#define CB_ZZ    66848                // 8192
#define CB_QPL   75040                // 1024
#define CB_HH    76064                // 1024
#define CB_UOP   77088
#define CB_UCOL  78112
#define CB_V3    79136
#define CB_TOPO  80160
#define CB_TOPC  81184
#define CB_RED   82208                // 256
#define CB_AOPS  82464                // 64
#define CB_ACOLS 82528                // 64
#define CB_SNUM  82592                // 32
#define CB_SOP   82624                // 9216  (opemb)
#define CB_SCOL  91840                // 16384 (colemb)
#define CB_SM1   108224               // 9216
#define CB_SM2   117440               // 16384
#define CB_SUV   133824               // 2048
#define C_SMEM   135872

__global__ void __launch_bounds__(CNT, 1)
k_core(const int* __restrict__ lwi_g, const int* __restrict__ nums_g,
       const float* __restrict__ opemb, const float* __restrict__ colemb,
       const float* __restrict__ Uv)
{
    extern __shared__ char smraw[];
    float* px    = (float*)(smraw + CB_PX);
    ull*   hb    = (ull*)(smraw + CB_HB);
    u32*  zmask  = (u32*)(smraw + CB_ZM);
    int*  slwi   = (int*)(smraw + CB_SL);
    float* zz    = (float*)(smraw + CB_ZZ);
    float* qpl   = (float*)(smraw + CB_QPL);
    float* hh    = (float*)(smraw + CB_HH);
    float* uop   = (float*)(smraw + CB_UOP);
    float* ucol  = (float*)(smraw + CB_UCOL);
    float* v3    = (float*)(smraw + CB_V3);
    float* topo  = (float*)(smraw + CB_TOPO);
    float* topc  = (float*)(smraw + CB_TOPC);
    float* red   = (float*)(smraw + CB_RED);
    float* aop_s = (float*)(smraw + CB_AOPS);
    float* acol_s= (float*)(smraw + CB_ACOLS);
    float* snum  = (float*)(smraw + CB_SNUM);
    float* sop   = (float*)(smraw + CB_SOP);
    float* scol  = (float*)(smraw + CB_SCOL);
    float* sM1   = (float*)(smraw + CB_SM1);
    float* sM2   = (float*)(smraw + CB_SM2);
    float* sUv   = (float*)(smraw + CB_SUV);

    int tid = threadIdx.x;
    int w = tid >> 5, lane = tid & 31, wrp = w;
    int lg = lane >> 2, lt = lane & 3;

    if (tid < NNUM) { slwi[tid] = lwi_g[tid]; snum[tid] = (float)nums_g[tid]; }
    if (tid < 64) hb[tid] = 0ull;
    if (tid < HID) hh[tid] = 0.f;
    {
        const float4* src = (const float4*)g_px;
        float4* dst = (float4*)px;
        for (int q = tid; q < QLEN * HID / 4; q += CNT) dst[q] = src[q];
    }
    for (int q = tid; q < NOPS * HID; q += CNT)  sop[q]  = opemb[q];
    for (int q = tid; q < NCOLS * HID; q += CNT) scol[q] = colemb[q];
    for (int q = tid; q < HID * NOPS; q += CNT)  sM1[q]  = g_M1[q];
    for (int q = tid; q < HID * NCOLS; q += CNT) sM2[q]  = g_M2[q];
    for (int q = tid; q < 2 * HID; q += CNT)     sUv[q]  = Uv[q];

    u32 aF[64];
#pragma unroll
    for (int q = 0; q < 64; q++) aF[q] = g_whf[q * 512 + tid];
    __syncthreads();
    if (tid < QLEN) {
        u32 m = 0;
#pragma unroll
        for (int n = 0; n < NNUM; n++)
            if (slwi[n] == tid) m |= (1u << n);
        zmask[tid] = m;
    }
    __syncthreads();

    // ---- Phase 1: RNN (64 steps) ----
    int m1 = 16 * w + lg;
    for (int step = 0; step < QLEN; step++) {
        const ull* hbc = hb + (step & 1) * 64;
        float d0[4] = {0.f,0.f,0.f,0.f}, d1[4] = {0.f,0.f,0.f,0.f};
        float d2[4] = {0.f,0.f,0.f,0.f}, d3[4] = {0.f,0.f,0.f,0.f};
#pragma unroll
        for (int kt = 0; kt < 16; kt++) {
            ull bb = hbc[kt * 4 + lt];
            u32 b0 = (u32)bb, b1 = (u32)(bb >> 32);
            float* dg = (kt & 3) == 0 ? d0 : (kt & 3) == 1 ? d1 : (kt & 3) == 2 ? d2 : d3;
            mma_bf16(dg, aF[4*kt], aF[4*kt+1], aF[4*kt+2], aF[4*kt+3], b0, b1);
        }
        float s0 = (d0[0] + d1[0]) + (d2[0] + d3[0]);
        float s2 = (d0[2] + d1[2]) + (d2[2] + d3[2]);
        float v1 = tanha(s0 + px[step * HID + m1]);
        float v2 = tanha(s2 + px[step * HID + m1 + 8]);
        float v1n = __shfl_down_sync(0xffffffffu, v1, 4);
        float v2n = __shfl_down_sync(0xffffffffu, v2, 4);
        if (lt == 0 && (lg & 1) == 0) {
            hb[((step + 1) & 1) * 64 + w * 4 + (lg >> 1)] =
                pack2u(bf2u(v1, v1n), bf2u(v2, v2n));
        }
        u32 m = zmask[step];
        if (lt == 0) {
            if (m) {
#pragma unroll
                for (int n = 0; n < NNUM; n++)
                    if ((m >> n) & 1u) {
                        zz[n * HID + m1] = v1;
                        zz[n * HID + m1 + 8] = v2;
                    }
            }
            if (step == QLEN - 1) { qpl[m1] = v1; qpl[m1 + 8] = v2; }
        }
        __syncthreads();
    }

    // ---- Phase 2: pivots ----
    {
        int p = wrp >> 3, n = wrp & 7;
        float s = 0.f;
#pragma unroll
        for (int j = 0; j < HID / 32; j++)
            s += zz[n * HID + j * 32 + lane] * sUv[p * HID + j * 32 + lane];
#pragma unroll
        for (int o = 16; o; o >>= 1) s += __shfl_xor_sync(0xffffffffu, s, o);
        if (lane == 0) red[p * 8 + n] = s;
    }
    __syncthreads();
    if (tid == 0) {
#pragma unroll
        for (int p = 0; p < 2; p++) {
            float m = -1e30f;
            for (int n = 0; n < 8; n++) m = fmaxf(m, red[p * 8 + n]);
            float den = 0.f, num = 0.f;
            for (int n = 0; n < 8; n++) {
                float e = expf(red[p * 8 + n] - m);
                den += e; num += e * snum[n];
            }
            g_piv[p] = num / den;
        }
    }

    // ---- Phase 3: uop/ucol (coalesced transposed bf16 chunks 0,2) ----
    int r = tid >> 1, kh = tid & 1;
    {
        const uint4* wa4 = g_wsel;              // Wop cols 0:256
        const uint4* wb4 = g_wsel + 2 * 8192;   // Wcol cols 0:256
        const ulonglong2* q2 = (const ulonglong2*)(qpl + kh * 128);
        ull a1 = 0ull, a2 = 0ull, b1a = 0ull, b2 = 0ull;
#pragma unroll
        for (int i = 0; i < 16; i++) {
            uint4 wa = wa4[i * 512 + tid], wb = wb4[i * 512 + tid];
            ulonglong2 h2a = q2[2*i], h2b = q2[2*i + 1];
            fma2(a1, bfexp(wa.x), h2a.x); fma2(a2, bfexp(wa.y), h2a.y);
            fma2(a1, bfexp(wa.z), h2b.x); fma2(a2, bfexp(wa.w), h2b.y);
            fma2(b1a, bfexp(wb.x), h2a.x); fma2(b2, bfexp(wb.y), h2a.y);
            fma2(b1a, bfexp(wb.z), h2b.x); fma2(b2, bfexp(wb.w), h2b.y);
        }
        float2 fa = unpack2(a1), fb = unpack2(a2);
        float2 fc = unpack2(b1a), fd = unpack2(b2);
        float s1 = (fa.x + fa.y) + (fb.x + fb.y);
        float s2 = (fc.x + fc.y) + (fd.x + fd.y);
        s1 += __shfl_xor_sync(0xffffffffu, s1, 1);
        s2 += __shfl_xor_sync(0xffffffffu, s2, 1);
        if (kh == 0) { uop[r] = s1; ucol[r] = s2; }
    }
    __syncthreads();

    // ---- Phase 4: selector chain (coalesced bf16 chunks 1,3,4) ----
    for (int t = 0; t < TSTEPS; t++) {
        {
            const uint4* a4 = g_wsel + 1 * 8192;
            const uint4* b4 = g_wsel + 3 * 8192;
            const uint4* c4 = g_wsel + 4 * 8192;
            const ulonglong2* h2 = (const ulonglong2*)(hh + kh * 128);
            ull s1a = 0ull, s1b = 0ull, s2a = 0ull, s2b = 0ull, s3a = 0ull, s3b = 0ull;
#pragma unroll
            for (int i = 0; i < 16; i++) {
                uint4 wa = a4[i * 512 + tid], wb = b4[i * 512 + tid], wc = c4[i * 512 + tid];
                ulonglong2 h2a = h2[2*i], h2b = h2[2*i + 1];
                fma2(s1a, bfexp(wa.x), h2a.x); fma2(s1b, bfexp(wa.y), h2a.y);
                fma2(s1a, bfexp(wa.z), h2b.x); fma2(s1b, bfexp(wa.w), h2b.y);
                fma2(s2a, bfexp(wb.x), h2a.x); fma2(s2b, bfexp(wb.y), h2a.y);
                fma2(s2a, bfexp(wb.z), h2b.x); fma2(s2b, bfexp(wb.w), h2b.y);
                fma2(s3a, bfexp(wc.x), h2a.x); fma2(s3b, bfexp(wc.y), h2a.y);
                fma2(s3a, bfexp(wc.z), h2b.x); fma2(s3b, bfexp(wc.w), h2b.y);
            }
            float2 f1 = unpack2(s1a), f1b = unpack2(s1b);
            float2 f2 = unpack2(s2a), f2b = unpack2(s2b);
            float2 f3 = unpack2(s3a), f3b = unpack2(s3b);
            float s1 = (f1.x + f1.y) + (f1b.x + f1b.y);
            float s2 = (f2.x + f2.y) + (f2b.x + f2b.y);
            float s3 = (f3.x + f3.y) + (f3b.x + f3b.y);
            s1 += __shfl_xor_sync(0xffffffffu, s1, 1);
            s2 += __shfl_xor_sync(0xffffffffu, s2, 1);
            s3 += __shfl_xor_sync(0xffffffffu, s3, 1);
            if (kh == 0) {
                topo[r] = tanha(uop[r] + s1);
                topc[r] = tanha(ucol[r] + s2);
                v3[r]   = s3;
            }
        }
        __syncthreads();
        if (wrp < NOPS) {
            float s = 0.f;
#pragma unroll
            for (int j = 0; j < HID / 32; j++)
                s += sop[wrp * HID + j * 32 + lane] * topo[j * 32 + lane];
#pragma unroll
            for (int o = 16; o; o >>= 1) s += __shfl_xor_sync(0xffffffffu, s, o);
            if (lane == 0) red[wrp] = s;
        }
        {
            float s = 0.f;
#pragma unroll
            for (int j = 0; j < HID / 32; j++)
                s += scol[wrp * HID + j * 32 + lane] * topc[j * 32 + lane];
#pragma unroll
            for (int o = 16; o; o >>= 1) s += __shfl_xor_sync(0xffffffffu, s, o);
            if (lane == 0) red[32 + wrp] = s;
        }
        __syncthreads();
        if (tid == 0) {
            float m = -1e30f;
            for (int o = 0; o < NOPS; o++) m = fmaxf(m, red[o]);
            float den = 0.f, e[NOPS];
            for (int o = 0; o < NOPS; o++) { e[o] = expf(red[o] - m); den += e[o]; }
            for (int o = 0; o < NOPS; o++) {
                float a = e[o] / den; aop_s[o] = a; g_aop[t * NOPS + o] = a;
            }
        }
        if (tid == 32) {
            float m = -1e30f;
            for (int c = 0; c < NCOLS; c++) m = fmaxf(m, red[32 + c]);
            float den = 0.f, e[NCOLS];
            for (int c = 0; c < NCOLS; c++) { e[c] = expf(red[32 + c] - m); den += e[c]; }
            for (int c = 0; c < NCOLS; c++) {
                float a = e[c] / den; acol_s[c] = a; g_acol[t * NCOLS + c] = a;
            }
        }
        __syncthreads();
        if (tid < HID) {
            float a = v3[tid];
#pragma unroll
            for (int o = 0; o < NOPS; o++)  a += sM1[tid * NOPS + o] * aop_s[o];
#pragma unroll
            for (int c = 0; c < NCOLS; c++) a += sM2[tid * NCOLS + c] * acol_s[c];
            hh[tid] = tanha(a);
        }
        __syncthreads();
    }
}

// ============================================================
// k_table: fused table pass + final reduction (last-block-done)
// ============================================================
#define K3T 256
__global__ void __launch_bounds__(K3T, 4)
k_table(const float* __restrict__ table, float* __restrict__ out, long rows)
{
    __shared__ ull   cf2[TSTEPS * NCOLS];
    __shared__ float cAnd[TSTEPS], cOr[TSTEPS], cRst[TSTEPS], cPass[TSTEPS];
    __shared__ float lkv[NCOLS];
    __shared__ float spv[2];
    __shared__ float wred[8 * 7];
    __shared__ int   sdone;
    __shared__ double sredd[7];

    int tid = threadIdx.x;
    if (tid < TSTEPS * NCOLS) {
        int t = tid >> 4, c = tid & 15;
        float ac = g_acol[t * NCOLS + c];
        cf2[tid] = pack2(g_aop[t * NOPS + 3] * ac, g_aop[t * NOPS + 4] * ac);
    } else if (tid < 64 + TSTEPS) {
        int t = tid - 64;
        cAnd[t]  = g_aop[t * NOPS + 5];
        cOr[t]   = g_aop[t * NOPS + 6];
        cRst[t]  = g_aop[t * NOPS + 8];
        cPass[t] = g_aop[t * NOPS + 0] + g_aop[t * NOPS + 1]
                 + g_aop[t * NOPS + 2] + g_aop[t * NOPS + 7];
    } else if (tid >= 96 && tid < 96 + NCOLS) {
        lkv[tid - 96] = g_aop[3 * NOPS + 7] * g_acol[3 * NCOLS + (tid - 96)];
    } else if (tid == 112) {
        spv[0] = g_piv[0]; spv[1] = g_piv[1];
    }
    __syncthreads();
    float lp = spv[0], gp = spv[1];
    int lane = tid & 31;
    float lkc = lkv[lane & 15];

    float accA = 0.f, aW0 = 0.f, aW1 = 0.f, aW2 = 0.f;
    float aC0 = 0.f, aC1 = 0.f, aC2 = 0.f;

    long stride = (long)gridDim.x * K3T;
    for (long base = (long)blockIdx.x * K3T; base < rows; base += stride) {
        long r = base + tid;
        float p1 = 0.f;
        if (r < rows) {
            const float4* tp = (const float4*)(table + r * NCOLS);
            float4 v0 = __ldcg(tp + 0), v1 = __ldcg(tp + 1);
            float4 v2 = __ldcg(tp + 2), v3r = __ldcg(tp + 3);
            float tv[16] = { v0.x, v0.y, v0.z, v0.w,  v1.x, v1.y, v1.z, v1.w,
                             v2.x, v2.y, v2.z, v2.w,  v3r.x, v3r.y, v3r.z, v3r.w };
            float rowsum = 0.f;
            ull acc0 = 0ull, acc1 = 0ull, acc2 = 0ull, acc3 = 0ull;
#pragma unroll
            for (int c = 0; c < 16; c++) {
                float v = tv[c];
                rowsum += v;
                float sg = fmaf(0.5f, tanha(0.5f * (v - gp)), 0.5f);
                float sl = fmaf(-0.5f, tanha(0.5f * (v - lp)), 0.5f);
                ull x = pack2(sg, sl);
                fma2(acc0, x, cf2[c]);
                fma2(acc1, x, cf2[16 + c]);
                fma2(acc2, x, cf2[32 + c]);
                fma2(acc3, x, cf2[48 + c]);
            }
            float2 d0 = unpack2(acc0), d1 = unpack2(acc1);
            float2 d2 = unpack2(acc2), d3 = unpack2(acc3);
            float d[4] = { d0.x + d0.y, d1.x + d1.y, d2.x + d2.y, d3.x + d3.y };
            accA += rowsum;
            float q1 = 1.f, q2 = 1.f;
#pragma unroll
            for (int t = 0; t < 4; t++) {
                float rs = d[t] + cAnd[t] * fminf(q1, q2)
                         + cOr[t] * fmaxf(q1, q2) + cRst[t] + cPass[t] * q1;
                if (t == 0) { aW0 += rs * rowsum; aC0 += rs; }
                else if (t == 1) { aW1 += rs * rowsum; aC1 += rs; }
                else if (t == 2) { aW2 += rs * rowsum; aC2 += rs; }
                q2 = q1; q1 = rs;
            }
            p1 = q1;
        }
        long rbase = base + (long)(tid & ~31);
        float* op = out + 1 + rbase * NCOLS;
#pragma unroll
        for (int m = 0; m < 16; m++) {
            int srcl = 2 * m + (lane >> 4);
            float v = __shfl_sync(0xffffffffu, p1, srcl);
            if (rbase + srcl < rows) op[m * 32 + lane] = v * lkc;
        }
    }

    float vals[7] = { accA, aW0, aW1, aW2, aC0, aC1, aC2 };
#pragma unroll
    for (int kk = 0; kk < 7; kk++) {
        float v = vals[kk];
#pragma unroll
        for (int o = 16; o; o >>= 1) v += __shfl_xor_sync(0xffffffffu, v, o);
        if ((tid & 31) == 0) wred[(tid >> 5) * 7 + kk] = v;
    }
    __syncthreads();
    if (tid < 7) {
        float s = 0.f;
        for (int wi = 0; wi < 8; wi++) s += wred[wi * 7 + tid];
        g_part[blockIdx.x * 8 + tid] = s;
    }
    __threadfence();
    __syncthreads();
    if (tid == 0) sdone = (atomicAdd(&g_ctr, 1u) == (u32)gridDim.x - 1u) ? 1 : 0;
    __syncthreads();
    if (!sdone) return;

    if (tid < 224) {
        int j = tid >> 5, ln = tid & 31;
        double s = 0.0;
        for (int b = ln; b < NBLK; b += 32) s += (double)g_part[b * 8 + j];
#pragma unroll
        for (int o = 16; o; o >>= 1) s += __shfl_xor_sync(0xffffffffu, s, o);
        if (ln == 0) sredd[j] = s;
    }
    __syncthreads();
    if (tid == 0) {
        double A   = sredd[0];
        double SW0 = sredd[1], SW1 = sredd[2], SW2 = sredd[3];
        double SC0 = sredd[4], SC1 = sredd[5], SC2 = sredd[6];
        const float* a0 = g_aop;
        const float* a1 = g_aop + NOPS;
        const float* a2 = g_aop + 2 * NOPS;
        const float* a3 = g_aop + 3 * NOPS;
        double s0 = (double)a0[0] * A   + (double)a0[1] * (double)rows;
        double s1 = (double)a1[0] * SW0 + (double)a1[1] * SC0 + (double)a1[2] * (0.0 - s0);
        double s2 = (double)a2[0] * SW1 + (double)a2[1] * SC1 + (double)a2[2] * (0.0 - s1);
        double s3 = (double)a3[0] * SW2 + (double)a3[1] * SC2 + (double)a3[2] * (s0 - s2);
        out[0] = (float)s3;
        g_ctr = 0u;
    }
}

// ============================================================
extern "C" void kernel_launch(void* const* d_in, const int* in_sizes, int n_in,
                              void* d_out, int out_size)
{
    const int*   qids   = (const int*)d_in[0];
    const int*   nums   = (const int*)d_in[1];
    const int*   lwi    = (const int*)d_in[2];
    const float* table  = (const float*)d_in[3];
    const float* emb    = (const float*)d_in[4];
    const float* Wx     = (const float*)d_in[5];
    const float* Wh     = (const float*)d_in[6];
    const float* Wop    = (const float*)d_in[7];
    const float* opemb  = (const float*)d_in[8];
    const float* Wcol   = (const float*)d_in[9];
    const float* colemb = (const float*)d_in[10];
    const float* Whist  = (const float*)d_in[11];
    const float* Uv     = (const float*)d_in[12];
    float* out = (float*)d_out;
    long rows = (long)in_sizes[3] / NCOLS;

    cudaFuncSetAttribute(k_core, cudaFuncAttributeMaxDynamicSharedMemorySize, C_SMEM);

    k_prep<<<233, 512>>>(qids, emb, Wx, Wh, Wop, Wcol, Whist, opemb, colemb);
    k_core<<<1, CNT, C_SMEM>>>(lwi, nums, opemb, colemb, Uv);
    k_table<<<NBLK, K3T>>>(table, out, rows);
}